// round 2
// baseline (speedup 1.0000x reference)
#include <cuda_runtime.h>

#define NB 2
#define SS 2048
#define HH 1024
#define NHEAD 16
#define HD 64
#define TOK (NB*SS)

// Scratch (device globals; no runtime allocation)
__device__ float g_Q[NB*NHEAD*SS*HD];   // [b,h,s,d], pre-scaled by 1/sqrt(64)
__device__ float g_K[NB*NHEAD*SS*HD];   // [b,h,s,d]
__device__ float g_V[NB*NHEAD*SS*HD];   // [b,h,s,d]
__device__ float g_ctx[TOK*HH];         // [b*s, h]

// ---------------------------------------------------------------------------
// Tiled SGEMM: C[M,N] = A[M,1024] * W[1024,N] + bias
// Block tile 128x128, K-tile 8, 256 threads, 8x8 micro-tile per thread.
// QKV=true: scatter into g_Q/g_K/g_V head layout.  QKV=false: A = g_ctx, write out.
// ---------------------------------------------------------------------------
template<int N, bool QKV>
__global__ __launch_bounds__(256) void gemm_k(const float* __restrict__ A,
                                              const float* __restrict__ W,
                                              const float* __restrict__ bias,
                                              float* __restrict__ out)
{
    __shared__ float As[8][128];
    __shared__ float Bs[8][128];
    const int tid = threadIdx.x;
    const int m0 = blockIdx.y * 128;
    const int n0 = blockIdx.x * 128;
    const int tx = tid & 15, ty = tid >> 4;
    const int arow = tid >> 1, acol = (tid & 1) << 2;   // A: 128 rows x 8 cols
    const int brow = tid >> 5, bcol = (tid & 31) << 2;  // B: 8 rows x 128 cols
    const float* __restrict__ Ap = QKV ? A : (const float*)g_ctx;

    float acc[8][8];
    #pragma unroll
    for (int i = 0; i < 8; i++)
        #pragma unroll
        for (int j = 0; j < 8; j++) acc[i][j] = 0.0f;

    for (int k0 = 0; k0 < 1024; k0 += 8) {
        float4 av = *(const float4*)(Ap + (size_t)(m0 + arow) * 1024 + k0 + acol);
        As[acol+0][arow] = av.x;
        As[acol+1][arow] = av.y;
        As[acol+2][arow] = av.z;
        As[acol+3][arow] = av.w;
        *(float4*)(&Bs[brow][bcol]) = *(const float4*)(W + (size_t)(k0 + brow) * N + n0 + bcol);
        __syncthreads();
        #pragma unroll
        for (int kk = 0; kk < 8; kk++) {
            float a[8], b[8];
            #pragma unroll
            for (int i = 0; i < 8; i++) a[i] = As[kk][ty*8 + i];
            #pragma unroll
            for (int j = 0; j < 8; j++) b[j] = Bs[kk][tx*8 + j];
            #pragma unroll
            for (int i = 0; i < 8; i++)
                #pragma unroll
                for (int j = 0; j < 8; j++) acc[i][j] += a[i] * b[j];
        }
        __syncthreads();
    }

    float bj[8];
    #pragma unroll
    for (int j = 0; j < 8; j++) bj[j] = bias[n0 + tx*8 + j];

    if (QKV) {
        #pragma unroll
        for (int i = 0; i < 8; i++) {
            int row = m0 + ty*8 + i;
            int b_ = row >> 11;        // / 2048
            int s_ = row & 2047;
            #pragma unroll
            for (int j = 0; j < 8; j++) {
                int col = n0 + tx*8 + j;
                float v = acc[i][j] + bj[j];
                int which = col >> 10;       // 0=Q 1=K 2=V
                int c = col & 1023;
                int idx = ((b_ * NHEAD + (c >> 6)) * SS + s_) * HD + (c & 63);
                if (which == 0)      g_Q[idx] = v * 0.125f;  // fold 1/sqrt(64)
                else if (which == 1) g_K[idx] = v;
                else                 g_V[idx] = v;
            }
        }
    } else {
        #pragma unroll
        for (int i = 0; i < 8; i++) {
            int row = m0 + ty*8 + i;
            #pragma unroll
            for (int j = 0; j < 8; j++) {
                int col = n0 + tx*8 + j;
                out[(size_t)row * 1024 + col] = acc[i][j] + bj[j];
            }
        }
    }
}

// ---------------------------------------------------------------------------
// Causal flash attention: one block per (q-tile 64, b*h). 8 warps x 8 rows.
// Each lane owns columns {lane, lane+32} and output dims {lane, lane+32}.
// K stored transposed in smem (KT[d][col]) => conflict-free score loads.
// ---------------------------------------------------------------------------
__global__ __launch_bounds__(256) void attn_k()
{
    extern __shared__ float sm[];
    float* Qs = sm;             // [64][64]
    float* KT = sm + 4096;      // [d][col]
    float* Vs = sm + 8192;      // [k][d]
    float* Ps = sm + 12288;     // [row][col] probs, rows warp-exclusive

    const int bh = blockIdx.y;
    const int qt = (int)gridDim.x - 1 - (int)blockIdx.x;  // heavy tiles first
    const int q0 = qt * 64;
    const float* __restrict__ Qg = g_Q + (size_t)bh * SS * HD + (size_t)q0 * HD;
    const float* __restrict__ Kg = g_K + (size_t)bh * SS * HD;
    const float* __restrict__ Vg = g_V + (size_t)bh * SS * HD;
    const int tid = threadIdx.x, lane = tid & 31, warp = tid >> 5;
    const int c0 = lane, c1 = lane + 32;

    for (int i = tid; i < 1024; i += 256)
        ((float4*)Qs)[i] = ((const float4*)Qg)[i];

    float mr[8], lr[8], oA[8], oB[8];
    #pragma unroll
    for (int r = 0; r < 8; r++) { mr[r] = -1e30f; lr[r] = 0.f; oA[r] = 0.f; oB[r] = 0.f; }

    for (int kt = 0; kt <= qt; kt++) {
        __syncthreads();   // previous tile's PV reads done before overwrite
        const float* __restrict__ Kt = Kg + (size_t)kt * 64 * HD;
        const float* __restrict__ Vt = Vg + (size_t)kt * 64 * HD;
        for (int i = tid; i < 1024; i += 256) {
            int krow = i >> 4;
            int dg = (i & 15) << 2;
            float4 kv = *(const float4*)(Kt + krow * HD + dg);
            KT[(dg+0)*64 + krow] = kv.x;
            KT[(dg+1)*64 + krow] = kv.y;
            KT[(dg+2)*64 + krow] = kv.z;
            KT[(dg+3)*64 + krow] = kv.w;
            ((float4*)Vs)[i] = ((const float4*)Vt)[i];
        }
        __syncthreads();

        // ---- scores: s[r][c] = sum_d Q[row][d] * K[col][d] ----
        float s[8][2];
        #pragma unroll
        for (int r = 0; r < 8; r++) { s[r][0] = 0.f; s[r][1] = 0.f; }
        #pragma unroll 4
        for (int d = 0; d < 64; d += 2) {
            float kA0 = KT[d*64 + c0],     kB0 = KT[d*64 + c1];
            float kA1 = KT[(d+1)*64 + c0], kB1 = KT[(d+1)*64 + c1];
            #pragma unroll
            for (int r = 0; r < 8; r++) {
                float2 q = *(const float2*)(Qs + (warp*8 + r)*64 + d);
                s[r][0] += q.x * kA0 + q.y * kA1;
                s[r][1] += q.x * kB0 + q.y * kB1;
            }
        }

        // ---- online softmax per row ----
        const bool diag = (kt == qt);
        #pragma unroll
        for (int r = 0; r < 8; r++) {
            int row = warp*8 + r;
            float s0 = s[r][0], s1 = s[r][1];
            if (diag) {
                if (c0 > row) s0 = -1e30f;
                if (c1 > row) s1 = -1e30f;
            }
            float mx = fmaxf(s0, s1);
            #pragma unroll
            for (int off = 16; off; off >>= 1)
                mx = fmaxf(mx, __shfl_xor_sync(0xffffffffu, mx, off));
            float nm = fmaxf(mr[r], mx);
            float p0 = __expf(s0 - nm);
            float p1 = __expf(s1 - nm);
            float corr = __expf(mr[r] - nm);
            mr[r] = nm;
            float ps = p0 + p1;
            #pragma unroll
            for (int off = 16; off; off >>= 1)
                ps += __shfl_xor_sync(0xffffffffu, ps, off);
            lr[r] = lr[r] * corr + ps;
            oA[r] *= corr; oB[r] *= corr;
            Ps[row*64 + c0] = p0;
            Ps[row*64 + c1] = p1;
        }
        __syncwarp();

        // ---- PV accumulate: o[row][d] += sum_k P[row][k] * V[k][d] ----
        #pragma unroll 4
        for (int k = 0; k < 64; k += 2) {
            float vA0 = Vs[k*64 + c0],     vB0 = Vs[k*64 + c1];
            float vA1 = Vs[(k+1)*64 + c0], vB1 = Vs[(k+1)*64 + c1];
            #pragma unroll
            for (int r = 0; r < 8; r++) {
                float2 p = *(const float2*)(Ps + (warp*8 + r)*64 + k);
                oA[r] += p.x * vA0 + p.y * vA1;
                oB[r] += p.x * vB0 + p.y * vB1;
            }
        }
    }

    // ---- epilogue: ctx[b, s, h*64 + d] ----
    const int bb = bh >> 4, hh = bh & 15;
    #pragma unroll
    for (int r = 0; r < 8; r++) {
        int row = warp*8 + r;
        size_t t = (size_t)(bb * SS + q0 + row);
        float inv = 1.0f / lr[r];
        g_ctx[t * HH + hh*64 + c0] = oA[r] * inv;
        g_ctx[t * HH + hh*64 + c1] = oB[r] * inv;
    }
}

// ---------------------------------------------------------------------------
extern "C" void kernel_launch(void* const* d_in, const int* in_sizes, int n_in,
                              void* d_out, int out_size)
{
    const float* x     = (const float*)d_in[0];
    // d_in[1] = mask: exactly tril(ones) per reference; causal handled analytically.
    const float* W_qkv = (const float*)d_in[2];
    const float* b_qkv = (const float*)d_in[3];
    const float* W_o   = (const float*)d_in[4];
    const float* b_o   = (const float*)d_in[5];
    float* out = (float*)d_out;

    // 1) QKV projection + bias + head scatter (+ Q scale)
    gemm_k<3072, true><<<dim3(24, 32), 256>>>(x, W_qkv, b_qkv, nullptr);

    // 2) Causal flash attention
    cudaFuncSetAttribute(attn_k, cudaFuncAttributeMaxDynamicSharedMemorySize, 65536);
    attn_k<<<dim3(32, 32), 256, 65536>>>();

    // 3) Output projection + bias
    gemm_k<1024, false><<<dim3(8, 32), 256>>>(nullptr, W_o, b_o, out);
}

// round 4
// speedup vs baseline: 2.9407x; 2.9407x over previous
#include <cuda_runtime.h>
#include <cstdint>

#define NB 2
#define SS 2048
#define HH 1024
#define NHEAD 16
#define HD 64
#define TOK (NB*SS)

// Scratch (device globals; no runtime allocation)
__device__ float g_Q[NB*NHEAD*SS*HD];   // [b,h,s,d], pre-scaled by 1/sqrt(64)
__device__ float g_K[NB*NHEAD*SS*HD];
__device__ float g_V[NB*NHEAD*SS*HD];
__device__ float g_ctx[TOK*HH];         // [b*s, h]
__device__ float g_Wt[3072*1024];       // transposed weights [N][K] (reused)

// ---------------------------------------------------------------------------
// mma.sync m16n8k8 TF32 helpers (legacy HMMA path — plain sm_103 compatible)
// ---------------------------------------------------------------------------
__device__ __forceinline__ uint32_t tf32u(float x) {
    uint32_t u;
    asm("cvt.rna.tf32.f32 %0, %1;" : "=r"(u) : "f"(x));
    return u;
}
__device__ __forceinline__ float tf32f(float x) { return __uint_as_float(tf32u(x)); }
__device__ __forceinline__ float4 tf4(float4 v) {
    v.x = tf32f(v.x); v.y = tf32f(v.y); v.z = tf32f(v.z); v.w = tf32f(v.w);
    return v;
}
__device__ __forceinline__ void mma8(float* d, const uint32_t* a, const uint32_t* b) {
    asm volatile(
        "mma.sync.aligned.m16n8k8.row.col.f32.tf32.tf32.f32 "
        "{%0,%1,%2,%3}, {%4,%5,%6,%7}, {%8,%9}, {%0,%1,%2,%3};"
        : "+f"(d[0]), "+f"(d[1]), "+f"(d[2]), "+f"(d[3])
        : "r"(a[0]), "r"(a[1]), "r"(a[2]), "r"(a[3]), "r"(b[0]), "r"(b[1]));
}
__device__ __forceinline__ uint32_t fu(float x) { return __float_as_uint(x); }

// ---------------------------------------------------------------------------
// Weight transpose: Wt[n][k] = W[k][n]
// ---------------------------------------------------------------------------
template<int N>
__global__ void transpose_k(const float* __restrict__ W, float* __restrict__ Wt)
{
    __shared__ float t[32][33];
    const int x = threadIdx.x, y = threadIdx.y;
    const int n0 = blockIdx.x * 32, k0 = blockIdx.y * 32;
    #pragma unroll
    for (int j = 0; j < 32; j += 8)
        t[y + j][x] = W[(size_t)(k0 + y + j) * N + n0 + x];
    __syncthreads();
    #pragma unroll
    for (int j = 0; j < 32; j += 8)
        Wt[(size_t)(n0 + y + j) * 1024 + k0 + x] = t[x][y + j];
}

// ---------------------------------------------------------------------------
// TF32 mma.sync GEMM: D[M=4096, NTOT] = A[M,1024] * Wt^T + bias
// CTA 128x128, KC=32, 256 threads = 8 warps (2m x 4n), warp tile 64x32.
// Smem [row][k] stride 36 floats: coalesced LDG, conflict-free STS + frag LDS.
// ---------------------------------------------------------------------------
template<int NTOT, bool QKV>
__global__ __launch_bounds__(256) void tgemm(const float* __restrict__ A,
                                             const float* __restrict__ bias,
                                             float* __restrict__ out)
{
    __shared__ float As[128 * 36];
    __shared__ float Bs[128 * 36];
    const int tid = threadIdx.x, lane = tid & 31, warp = tid >> 5;
    const int g = lane >> 2, t = lane & 3;
    const int wm = warp >> 2, wn = warp & 3;       // 2 x 4 warp grid
    const int m0 = blockIdx.y * 128;
    const int n0 = blockIdx.x * 128;
    const float* __restrict__ Ap = QKV ? A : (const float*)g_ctx;
    const float* __restrict__ Bp = (const float*)g_Wt;

    const int lm = tid >> 3;            // 0..31
    const int lk = (tid & 7) * 4;       // 0,4,...,28

    float acc[4][4][4];
    #pragma unroll
    for (int mf = 0; mf < 4; mf++)
        #pragma unroll
        for (int nf = 0; nf < 4; nf++)
            #pragma unroll
            for (int c = 0; c < 4; c++) acc[mf][nf][c] = 0.0f;

    float4 ra[4], rb[4];
    #pragma unroll
    for (int j = 0; j < 4; j++) {
        ra[j] = *(const float4*)(Ap + (size_t)(m0 + lm + 32*j) * 1024 + lk);
        rb[j] = *(const float4*)(Bp + (size_t)(n0 + lm + 32*j) * 1024 + lk);
    }

    for (int it = 0; it < 32; ++it) {
        __syncthreads();
        #pragma unroll
        for (int j = 0; j < 4; j++) {
            *(float4*)&As[(lm + 32*j) * 36 + lk] = tf4(ra[j]);
            *(float4*)&Bs[(lm + 32*j) * 36 + lk] = tf4(rb[j]);
        }
        __syncthreads();
        if (it < 31) {
            const int kb = (it + 1) * 32;
            #pragma unroll
            for (int j = 0; j < 4; j++) {
                ra[j] = *(const float4*)(Ap + (size_t)(m0 + lm + 32*j) * 1024 + kb + lk);
                rb[j] = *(const float4*)(Bp + (size_t)(n0 + lm + 32*j) * 1024 + kb + lk);
            }
        }
        #pragma unroll
        for (int ks = 0; ks < 4; ks++) {
            const int k0 = ks * 8;
            uint32_t af[4][4];
            #pragma unroll
            for (int mf = 0; mf < 4; mf++) {
                const float* ab = &As[(wm*64 + mf*16 + g) * 36 + k0 + t];
                af[mf][0] = fu(ab[0]);
                af[mf][1] = fu(ab[8*36]);
                af[mf][2] = fu(ab[4]);
                af[mf][3] = fu(ab[8*36 + 4]);
            }
            #pragma unroll
            for (int nf = 0; nf < 4; nf++) {
                const float* bb = &Bs[(wn*32 + nf*8 + g) * 36 + k0 + t];
                uint32_t bf[2] = { fu(bb[0]), fu(bb[4]) };
                #pragma unroll
                for (int mf = 0; mf < 4; mf++) mma8(acc[mf][nf], af[mf], bf);
            }
        }
    }

    // Epilogue: scatter C fragments directly
    #pragma unroll
    for (int nf = 0; nf < 4; nf++) {
        const int col = n0 + wn*32 + nf*8 + 2*t;   // even; (col,col+1) same 64-block
        const float b0 = bias[col], b1 = bias[col + 1];
        if (QKV) {
            const int which = col >> 10;
            const int c = col & 1023;
            const int head = c >> 6, d0 = c & 63;
            const float scale = (which == 0) ? 0.125f : 1.0f;
            float* dst = (which == 0) ? g_Q : (which == 1) ? g_K : g_V;
            #pragma unroll
            for (int mf = 0; mf < 4; mf++) {
                #pragma unroll
                for (int h = 0; h < 2; h++) {
                    const int row = m0 + wm*64 + mf*16 + g + h*8;
                    const int b_ = row >> 11, s_ = row & 2047;
                    const size_t idx = ((size_t)(b_ * NHEAD + head) * SS + s_) * HD + d0;
                    float2 v;
                    v.x = (acc[mf][nf][2*h]   + b0) * scale;
                    v.y = (acc[mf][nf][2*h+1] + b1) * scale;
                    *(float2*)&dst[idx] = v;
                }
            }
        } else {
            #pragma unroll
            for (int mf = 0; mf < 4; mf++) {
                #pragma unroll
                for (int h = 0; h < 2; h++) {
                    const int row = m0 + wm*64 + mf*16 + g + h*8;
                    float2 v;
                    v.x = acc[mf][nf][2*h]   + b0;
                    v.y = acc[mf][nf][2*h+1] + b1;
                    *(float2*)&out[(size_t)row * 1024 + col] = v;
                }
            }
        }
    }
}

// ---------------------------------------------------------------------------
// Causal flash attention, tensorized (mma.sync tf32).
// CTA: 64x64 Q tile per (qt, b*h). 8 warps: mma grid 4m x 2n (warp tile 16x32);
// softmax grid: warp w owns rows w*8..w*8+8 (R1-verified reduction code).
// Smem rows stride 68 floats (conflict-free frags; V B-frags 2-way worst case).
// ---------------------------------------------------------------------------
#define QS 0
#define KS 4352
#define VS 8704
#define PS 13056
#define CORR 17408
#define LINV 17472
#define ATTN_SMEM ((17536) * 4)

__global__ __launch_bounds__(256) void attn_k()
{
    extern __shared__ float sm[];
    const int bh = blockIdx.y;
    const int qt = (int)gridDim.x - 1 - (int)blockIdx.x;  // heavy tiles first
    const int q0 = qt * 64;
    const float* __restrict__ Qg = g_Q + (size_t)bh * SS * HD + (size_t)q0 * HD;
    const float* __restrict__ Kg = g_K + (size_t)bh * SS * HD;
    const float* __restrict__ Vg = g_V + (size_t)bh * SS * HD;
    const int tid = threadIdx.x, lane = tid & 31, warp = tid >> 5;
    const int g = lane >> 2, t = lane & 3;
    const int wm = warp >> 1, wn = warp & 1;   // 4m x 2n mma grid

    // Load Q tile (tf32-rounded), row-major stride 68
    #pragma unroll
    for (int j = 0; j < 4; j++) {
        const int idx = tid + 256*j;
        const int row = idx >> 4, c4 = (idx & 15) * 4;
        *(float4*)&sm[QS + row*68 + c4] = tf4(*(const float4*)(Qg + row*64 + c4));
    }

    float o[4][4];
    #pragma unroll
    for (int nf = 0; nf < 4; nf++)
        #pragma unroll
        for (int c = 0; c < 4; c++) o[nf][c] = 0.0f;
    float mr[8], lr[8];
    #pragma unroll
    for (int r = 0; r < 8; r++) { mr[r] = -1e30f; lr[r] = 0.0f; }

    for (int kt = 0; kt <= qt; kt++) {
        __syncthreads();   // prev PV done with Vs/Ps
        const float* __restrict__ Kt = Kg + (size_t)kt * 64 * HD;
        const float* __restrict__ Vt = Vg + (size_t)kt * 64 * HD;
        #pragma unroll
        for (int j = 0; j < 4; j++) {
            const int idx = tid + 256*j;
            const int row = idx >> 4, c4 = (idx & 15) * 4;
            *(float4*)&sm[KS + row*68 + c4] = tf4(*(const float4*)(Kt + row*64 + c4));
            *(float4*)&sm[VS + row*68 + c4] = tf4(*(const float4*)(Vt + row*64 + c4));
        }
        __syncthreads();

        // ---- S = Q K^T via mma ----
        float sc[4][4];
        #pragma unroll
        for (int nf = 0; nf < 4; nf++)
            #pragma unroll
            for (int c = 0; c < 4; c++) sc[nf][c] = 0.0f;
        #pragma unroll
        for (int ks = 0; ks < 8; ks++) {
            const int k0 = ks * 8;
            uint32_t a[4];
            const float* qb = &sm[QS + (wm*16 + g)*68 + k0 + t];
            a[0] = fu(qb[0]); a[1] = fu(qb[8*68]); a[2] = fu(qb[4]); a[3] = fu(qb[8*68 + 4]);
            #pragma unroll
            for (int nf = 0; nf < 4; nf++) {
                const float* kb = &sm[KS + (wn*32 + nf*8 + g)*68 + k0 + t];
                uint32_t b[2] = { fu(kb[0]), fu(kb[4]) };
                mma8(sc[nf], a, b);
            }
        }
        // scatter S to Ps
        #pragma unroll
        for (int nf = 0; nf < 4; nf++) {
            const int c = wn*32 + nf*8 + 2*t;
            *(float2*)&sm[PS + (wm*16 + g)*68 + c]     = make_float2(sc[nf][0], sc[nf][1]);
            *(float2*)&sm[PS + (wm*16 + g + 8)*68 + c] = make_float2(sc[nf][2], sc[nf][3]);
        }
        __syncthreads();

        // ---- online softmax: warp w owns rows w*8..w*8+8 ----
        const bool diag = (kt == qt);
        #pragma unroll
        for (int r = 0; r < 8; r++) {
            const int row = warp*8 + r;
            float s0 = sm[PS + row*68 + lane];
            float s1 = sm[PS + row*68 + lane + 32];
            if (diag) {
                if (lane > row)      s0 = -1e30f;
                if (lane + 32 > row) s1 = -1e30f;
            }
            float mx = fmaxf(s0, s1);
            #pragma unroll
            for (int off = 16; off; off >>= 1)
                mx = fmaxf(mx, __shfl_xor_sync(0xffffffffu, mx, off));
            const float nm = fmaxf(mr[r], mx);
            const float p0 = __expf(s0 - nm);
            const float p1 = __expf(s1 - nm);
            const float corr = __expf(mr[r] - nm);
            mr[r] = nm;
            float ps = p0 + p1;
            #pragma unroll
            for (int off = 16; off; off >>= 1)
                ps += __shfl_xor_sync(0xffffffffu, ps, off);
            lr[r] = lr[r] * corr + ps;
            sm[PS + row*68 + lane]      = tf32f(p0);
            sm[PS + row*68 + lane + 32] = tf32f(p1);
            if (lane == 0) sm[CORR + row] = corr;
        }
        __syncthreads();

        // ---- O = O*corr + P V via mma ----
        const float co0 = sm[CORR + wm*16 + g];
        const float co1 = sm[CORR + wm*16 + g + 8];
        #pragma unroll
        for (int nf = 0; nf < 4; nf++) {
            o[nf][0] *= co0; o[nf][1] *= co0;
            o[nf][2] *= co1; o[nf][3] *= co1;
        }
        #pragma unroll
        for (int ks = 0; ks < 8; ks++) {
            const int k0 = ks * 8;
            uint32_t a[4];
            const float* pb = &sm[PS + (wm*16 + g)*68 + k0 + t];
            a[0] = fu(pb[0]); a[1] = fu(pb[8*68]); a[2] = fu(pb[4]); a[3] = fu(pb[8*68 + 4]);
            #pragma unroll
            for (int nf = 0; nf < 4; nf++) {
                const float* vb = &sm[VS + (k0 + t)*68 + wn*32 + nf*8 + g];
                uint32_t b[2] = { fu(vb[0]), fu(vb[4*68]) };
                mma8(o[nf], a, b);
            }
        }
    }

    // ---- epilogue ----
    #pragma unroll
    for (int r = 0; r < 8; r++)
        if (lane == 0) sm[LINV + warp*8 + r] = 1.0f / lr[r];
    __syncthreads();

    const int bb = bh >> 4, hh = bh & 15;
    #pragma unroll
    for (int nf = 0; nf < 4; nf++) {
        const int c = wn*32 + nf*8 + 2*t;
        #pragma unroll
        for (int h = 0; h < 2; h++) {
            const int row = wm*16 + g + h*8;
            const float li = sm[LINV + row];
            const size_t base = (size_t)(bb * SS + q0 + row) * HH + hh*64 + c;
            float2 v;
            v.x = o[nf][2*h]   * li;
            v.y = o[nf][2*h+1] * li;
            *(float2*)&g_ctx[base] = v;
        }
    }
}

// ---------------------------------------------------------------------------
extern "C" void kernel_launch(void* const* d_in, const int* in_sizes, int n_in,
                              void* d_out, int out_size)
{
    const float* x     = (const float*)d_in[0];
    // d_in[1] = mask: exactly tril(ones); causal handled analytically.
    const float* W_qkv = (const float*)d_in[2];
    const float* b_qkv = (const float*)d_in[3];
    const float* W_o   = (const float*)d_in[4];
    const float* b_o   = (const float*)d_in[5];
    float* out = (float*)d_out;

    float* wt;
    cudaGetSymbolAddress((void**)&wt, g_Wt);

    static bool attrs_set = false;
    if (!attrs_set) {
        cudaFuncSetAttribute(attn_k, cudaFuncAttributeMaxDynamicSharedMemorySize, ATTN_SMEM);
        attrs_set = true;
    }

    // 1) W_qkv^T, then QKV projection (mma.sync TF32) + bias + head scatter + Q scale
    transpose_k<3072><<<dim3(96, 32), dim3(32, 8)>>>(W_qkv, wt);
    tgemm<3072, true><<<dim3(24, 32), 256>>>(x, b_qkv, nullptr);

    // 2) Causal flash attention (mma.sync TF32)
    attn_k<<<dim3(32, 32), 256, ATTN_SMEM>>>();

    // 3) W_o^T, then output projection (mma.sync TF32) + bias
    transpose_k<1024><<<dim3(32, 32), dim3(32, 8)>>>(W_o, wt);
    tgemm<1024, false><<<dim3(8, 32), 256>>>(nullptr, b_o, out);
}

// round 5
// speedup vs baseline: 3.6035x; 1.2254x over previous
#include <cuda_runtime.h>
#include <cstdint>

#define NB 2
#define SS 2048
#define HH 1024
#define NHEAD 16
#define HD 64
#define TOK (NB*SS)

// Scratch (device globals; no runtime allocation)
__device__ float g_Q[NB*NHEAD*SS*HD];   // [b,h,s,d], pre-scaled by 1/sqrt(64)
__device__ float g_K[NB*NHEAD*SS*HD];
__device__ float g_V[NB*NHEAD*SS*HD];
__device__ float g_ctx[TOK*HH];         // [b*s, h]
__device__ float g_Wt[3072*1024];       // transposed weights [N][K] (reused)

// ---------------------------------------------------------------------------
// mma.sync m16n8k8 TF32 helpers (legacy HMMA path — plain sm_103 compatible)
// ---------------------------------------------------------------------------
__device__ __forceinline__ uint32_t tf32u(float x) {
    uint32_t u;
    asm("cvt.rna.tf32.f32 %0, %1;" : "=r"(u) : "f"(x));
    return u;
}
__device__ __forceinline__ float tf32f(float x) { return __uint_as_float(tf32u(x)); }
__device__ __forceinline__ float4 tf4(float4 v) {
    v.x = tf32f(v.x); v.y = tf32f(v.y); v.z = tf32f(v.z); v.w = tf32f(v.w);
    return v;
}
__device__ __forceinline__ void mma8(float* d, const uint32_t* a, const uint32_t* b) {
    asm volatile(
        "mma.sync.aligned.m16n8k8.row.col.f32.tf32.tf32.f32 "
        "{%0,%1,%2,%3}, {%4,%5,%6,%7}, {%8,%9}, {%0,%1,%2,%3};"
        : "+f"(d[0]), "+f"(d[1]), "+f"(d[2]), "+f"(d[3])
        : "r"(a[0]), "r"(a[1]), "r"(a[2]), "r"(a[3]), "r"(b[0]), "r"(b[1]));
}
__device__ __forceinline__ uint32_t fu(float x) { return __float_as_uint(x); }

// ---------------------------------------------------------------------------
// Weight transpose: Wt[n][k] = W[k][n]
// ---------------------------------------------------------------------------
template<int N>
__global__ void transpose_k(const float* __restrict__ W, float* __restrict__ Wt)
{
    __shared__ float t[32][33];
    const int x = threadIdx.x, y = threadIdx.y;
    const int n0 = blockIdx.x * 32, k0 = blockIdx.y * 32;
    #pragma unroll
    for (int j = 0; j < 32; j += 8)
        t[y + j][x] = W[(size_t)(k0 + y + j) * N + n0 + x];
    __syncthreads();
    #pragma unroll
    for (int j = 0; j < 32; j += 8)
        Wt[(size_t)(n0 + y + j) * 1024 + k0 + x] = t[x][y + j];
}

// ---------------------------------------------------------------------------
// TF32 mma.sync GEMM: D[M=4096, NTOT] = A[M,1024] * Wt^T + bias
// (unchanged from R4 — verified correct+fast)
// ---------------------------------------------------------------------------
template<int NTOT, bool QKV>
__global__ __launch_bounds__(256) void tgemm(const float* __restrict__ A,
                                             const float* __restrict__ bias,
                                             float* __restrict__ out)
{
    __shared__ float As[128 * 36];
    __shared__ float Bs[128 * 36];
    const int tid = threadIdx.x, lane = tid & 31, warp = tid >> 5;
    const int g = lane >> 2, t = lane & 3;
    const int wm = warp >> 2, wn = warp & 3;
    const int m0 = blockIdx.y * 128;
    const int n0 = blockIdx.x * 128;
    const float* __restrict__ Ap = QKV ? A : (const float*)g_ctx;
    const float* __restrict__ Bp = (const float*)g_Wt;

    const int lm = tid >> 3;
    const int lk = (tid & 7) * 4;

    float acc[4][4][4];
    #pragma unroll
    for (int mf = 0; mf < 4; mf++)
        #pragma unroll
        for (int nf = 0; nf < 4; nf++)
            #pragma unroll
            for (int c = 0; c < 4; c++) acc[mf][nf][c] = 0.0f;

    float4 ra[4], rb[4];
    #pragma unroll
    for (int j = 0; j < 4; j++) {
        ra[j] = *(const float4*)(Ap + (size_t)(m0 + lm + 32*j) * 1024 + lk);
        rb[j] = *(const float4*)(Bp + (size_t)(n0 + lm + 32*j) * 1024 + lk);
    }

    for (int it = 0; it < 32; ++it) {
        __syncthreads();
        #pragma unroll
        for (int j = 0; j < 4; j++) {
            *(float4*)&As[(lm + 32*j) * 36 + lk] = tf4(ra[j]);
            *(float4*)&Bs[(lm + 32*j) * 36 + lk] = tf4(rb[j]);
        }
        __syncthreads();
        if (it < 31) {
            const int kb = (it + 1) * 32;
            #pragma unroll
            for (int j = 0; j < 4; j++) {
                ra[j] = *(const float4*)(Ap + (size_t)(m0 + lm + 32*j) * 1024 + kb + lk);
                rb[j] = *(const float4*)(Bp + (size_t)(n0 + lm + 32*j) * 1024 + kb + lk);
            }
        }
        #pragma unroll
        for (int ks = 0; ks < 4; ks++) {
            const int k0 = ks * 8;
            uint32_t af[4][4];
            #pragma unroll
            for (int mf = 0; mf < 4; mf++) {
                const float* ab = &As[(wm*64 + mf*16 + g) * 36 + k0 + t];
                af[mf][0] = fu(ab[0]);
                af[mf][1] = fu(ab[8*36]);
                af[mf][2] = fu(ab[4]);
                af[mf][3] = fu(ab[8*36 + 4]);
            }
            #pragma unroll
            for (int nf = 0; nf < 4; nf++) {
                const float* bb = &Bs[(wn*32 + nf*8 + g) * 36 + k0 + t];
                uint32_t bf[2] = { fu(bb[0]), fu(bb[4]) };
                #pragma unroll
                for (int mf = 0; mf < 4; mf++) mma8(acc[mf][nf], af[mf], bf);
            }
        }
    }

    #pragma unroll
    for (int nf = 0; nf < 4; nf++) {
        const int col = n0 + wn*32 + nf*8 + 2*t;
        const float b0 = bias[col], b1 = bias[col + 1];
        if (QKV) {
            const int which = col >> 10;
            const int c = col & 1023;
            const int head = c >> 6, d0 = c & 63;
            const float scale = (which == 0) ? 0.125f : 1.0f;
            float* dst = (which == 0) ? g_Q : (which == 1) ? g_K : g_V;
            #pragma unroll
            for (int mf = 0; mf < 4; mf++) {
                #pragma unroll
                for (int h = 0; h < 2; h++) {
                    const int row = m0 + wm*64 + mf*16 + g + h*8;
                    const int b_ = row >> 11, s_ = row & 2047;
                    const size_t idx = ((size_t)(b_ * NHEAD + head) * SS + s_) * HD + d0;
                    float2 v;
                    v.x = (acc[mf][nf][2*h]   + b0) * scale;
                    v.y = (acc[mf][nf][2*h+1] + b1) * scale;
                    *(float2*)&dst[idx] = v;
                }
            }
        } else {
            #pragma unroll
            for (int mf = 0; mf < 4; mf++) {
                #pragma unroll
                for (int h = 0; h < 2; h++) {
                    const int row = m0 + wm*64 + mf*16 + g + h*8;
                    float2 v;
                    v.x = acc[mf][nf][2*h]   + b0;
                    v.y = acc[mf][nf][2*h+1] + b1;
                    *(float2*)&out[(size_t)row * 1024 + col] = v;
                }
            }
        }
    }
}

// ---------------------------------------------------------------------------
// Causal flash attention v2: Q-tile 128 x K-tile 64, 8 warps.
// Warp tile 16x64 — each warp owns its 16 rows end-to-end (mma S, register
// softmax within lane-quads, P in per-warp smem, mma PV). 3 syncs/iter.
// Strides: Q/K/P = 68 (banks g*4+t, conflict-free); V = 72 (banks t*8+g, cf).
// ---------------------------------------------------------------------------
#define AQ 0
#define AK (128*68)            // 8704
#define AV (AK + 64*68)        // 13056
#define AP (AV + 64*72)        // 17664
#define ATTN_FLOATS (AP + 8*16*68)   // 26368
#define ATTN_SMEM (ATTN_FLOATS * 4)  // 105472 B

__global__ __launch_bounds__(256, 2) void attn_k()
{
    extern __shared__ float sm[];
    const int bh = blockIdx.y;
    const int qt = (int)gridDim.x - 1 - (int)blockIdx.x;  // heavy tiles first
    const int q0 = qt * 128;
    const float* __restrict__ Qg = g_Q + (size_t)bh * SS * HD + (size_t)q0 * HD;
    const float* __restrict__ Kg = g_K + (size_t)bh * SS * HD;
    const float* __restrict__ Vg = g_V + (size_t)bh * SS * HD;
    const int tid = threadIdx.x, lane = tid & 31, warp = tid >> 5;
    const int g = lane >> 2, t = lane & 3;

    // loader mapping: 4 float4 per thread per 64x64 tile
    const int lrow = tid >> 2;            // used via idx below
    (void)lrow;

    // Load Q tile: 128x64 -> stride 68, tf32-rounded
    #pragma unroll
    for (int j = 0; j < 8; j++) {
        const int idx = tid + 256*j;
        const int row = idx >> 4, c4 = (idx & 15) * 4;
        *(float4*)&sm[AQ + row*68 + c4] = tf4(*(const float4*)(Qg + row*64 + c4));
    }

    float o[8][4];
    #pragma unroll
    for (int nf = 0; nf < 8; nf++)
        #pragma unroll
        for (int c = 0; c < 4; c++) o[nf][c] = 0.0f;
    float mr0 = -1e30f, mr1 = -1e30f, l0 = 0.0f, l1 = 0.0f;

    const int ktmax = 2*qt + 1;
    const int row0g = q0 + warp*16 + g;     // global row of frag-half 0
    float* __restrict__ Pw = &sm[AP + warp*16*68];

    // prefetch K tile 0
    float4 kreg[4];
    #pragma unroll
    for (int j = 0; j < 4; j++) {
        const int idx = tid + 256*j;
        const int row = idx >> 4, c4 = (idx & 15) * 4;
        kreg[j] = *(const float4*)(Kg + row*64 + c4);
    }

    for (int kt = 0; kt <= ktmax; kt++) {
        __syncthreads();   // prev PV done reading VS; prev S done reading KS
        float4 vreg[4];
        #pragma unroll
        for (int j = 0; j < 4; j++) {
            const int idx = tid + 256*j;
            const int row = idx >> 4, c4 = (idx & 15) * 4;
            sm[AK + row*68 + c4 + 0] = tf32f(kreg[j].x);
            sm[AK + row*68 + c4 + 1] = tf32f(kreg[j].y);
            sm[AK + row*68 + c4 + 2] = tf32f(kreg[j].z);
            sm[AK + row*68 + c4 + 3] = tf32f(kreg[j].w);
            vreg[j] = *(const float4*)(Vg + (size_t)kt*64*HD + row*64 + c4);
        }
        __syncthreads();   // KS visible

        // warp entirely above the diagonal for this key tile? -> identity
        const bool active = (kt*64 <= row0g + 15 - g + g); // kt*64 <= q0+warp*16+15
        const bool act = (kt*64 <= q0 + warp*16 + 15);

        if (act) {
            // ---- S = Q K^T ----
            float sc[8][4];
            #pragma unroll
            for (int nf = 0; nf < 8; nf++)
                #pragma unroll
                for (int c = 0; c < 4; c++) sc[nf][c] = 0.0f;
            #pragma unroll
            for (int ks = 0; ks < 8; ks++) {
                const int k0 = ks * 8;
                uint32_t a[4];
                const float* qb = &sm[AQ + (warp*16 + g)*68 + k0 + t];
                a[0] = fu(qb[0]); a[1] = fu(qb[8*68]); a[2] = fu(qb[4]); a[3] = fu(qb[8*68 + 4]);
                #pragma unroll
                for (int nf = 0; nf < 8; nf++) {
                    const float* kb = &sm[AK + (nf*8 + g)*68 + k0 + t];
                    uint32_t b[2] = { fu(kb[0]), fu(kb[4]) };
                    mma8(sc[nf], a, b);
                }
            }
            // ---- causal mask (only the last two key tiles can intersect) ----
            if (kt >= 2*qt) {
                #pragma unroll
                for (int nf = 0; nf < 8; nf++) {
                    const int key = kt*64 + nf*8 + 2*t;
                    if (key     > row0g)     sc[nf][0] = -1e30f;
                    if (key + 1 > row0g)     sc[nf][1] = -1e30f;
                    if (key     > row0g + 8) sc[nf][2] = -1e30f;
                    if (key + 1 > row0g + 8) sc[nf][3] = -1e30f;
                }
            }
            // ---- register online softmax (rows g, g+8; quad-reduce) ----
            float mx0 = -1e30f, mx1 = -1e30f;
            #pragma unroll
            for (int nf = 0; nf < 8; nf++) {
                mx0 = fmaxf(mx0, fmaxf(sc[nf][0], sc[nf][1]));
                mx1 = fmaxf(mx1, fmaxf(sc[nf][2], sc[nf][3]));
            }
            mx0 = fmaxf(mx0, __shfl_xor_sync(0xffffffffu, mx0, 1));
            mx0 = fmaxf(mx0, __shfl_xor_sync(0xffffffffu, mx0, 2));
            mx1 = fmaxf(mx1, __shfl_xor_sync(0xffffffffu, mx1, 1));
            mx1 = fmaxf(mx1, __shfl_xor_sync(0xffffffffu, mx1, 2));
            const float nm0 = fmaxf(mr0, mx0);
            const float nm1 = fmaxf(mr1, mx1);
            const float c0 = __expf(mr0 - nm0);
            const float c1 = __expf(mr1 - nm1);
            mr0 = nm0; mr1 = nm1;
            float s0 = 0.0f, s1 = 0.0f;
            #pragma unroll
            for (int nf = 0; nf < 8; nf++) {
                sc[nf][0] = __expf(sc[nf][0] - nm0); s0 += sc[nf][0];
                sc[nf][1] = __expf(sc[nf][1] - nm0); s0 += sc[nf][1];
                sc[nf][2] = __expf(sc[nf][2] - nm1); s1 += sc[nf][2];
                sc[nf][3] = __expf(sc[nf][3] - nm1); s1 += sc[nf][3];
            }
            s0 += __shfl_xor_sync(0xffffffffu, s0, 1);
            s0 += __shfl_xor_sync(0xffffffffu, s0, 2);
            s1 += __shfl_xor_sync(0xffffffffu, s1, 1);
            s1 += __shfl_xor_sync(0xffffffffu, s1, 2);
            l0 = l0 * c0 + s0;
            l1 = l1 * c1 + s1;
            #pragma unroll
            for (int nf = 0; nf < 8; nf++) {
                o[nf][0] *= c0; o[nf][1] *= c0;
                o[nf][2] *= c1; o[nf][3] *= c1;
            }
            // ---- P -> per-warp smem (tf32-rounded) ----
            #pragma unroll
            for (int nf = 0; nf < 8; nf++) {
                *(float2*)&Pw[g*68 + nf*8 + 2*t] =
                    make_float2(tf32f(sc[nf][0]), tf32f(sc[nf][1]));
                *(float2*)&Pw[(g+8)*68 + nf*8 + 2*t] =
                    make_float2(tf32f(sc[nf][2]), tf32f(sc[nf][3]));
            }
        }
        (void)active;

        // ---- STS V (stride 72), prefetch next K ----
        #pragma unroll
        for (int j = 0; j < 4; j++) {
            const int idx = tid + 256*j;
            const int row = idx >> 4, c4 = (idx & 15) * 4;
            sm[AV + row*72 + c4 + 0] = tf32f(vreg[j].x);
            sm[AV + row*72 + c4 + 1] = tf32f(vreg[j].y);
            sm[AV + row*72 + c4 + 2] = tf32f(vreg[j].z);
            sm[AV + row*72 + c4 + 3] = tf32f(vreg[j].w);
            if (kt < ktmax)
                kreg[j] = *(const float4*)(Kg + (size_t)(kt+1)*64*HD + row*64 + c4);
        }
        __syncthreads();   // VS + own P visible

        if (act) {
            // ---- O += P V ----
            #pragma unroll
            for (int ks = 0; ks < 8; ks++) {
                const int k0 = ks * 8;
                uint32_t a[4];
                const float* pb = &Pw[g*68 + k0 + t];
                a[0] = fu(pb[0]); a[1] = fu(pb[8*68]); a[2] = fu(pb[4]); a[3] = fu(pb[8*68 + 4]);
                #pragma unroll
                for (int nf = 0; nf < 8; nf++) {
                    const float* vb = &sm[AV + (k0 + t)*72 + nf*8 + g];
                    uint32_t b[2] = { fu(vb[0]), fu(vb[4*72]) };
                    mma8(o[nf], a, b);
                }
            }
        }
    }

    // ---- epilogue ----
    const float i0 = 1.0f / l0, i1 = 1.0f / l1;
    const int bb = bh >> 4, hh = bh & 15;
    #pragma unroll
    for (int nf = 0; nf < 8; nf++) {
        const int col = hh*64 + nf*8 + 2*t;
        const size_t b0 = (size_t)(bb * SS + row0g) * HH + col;
        const size_t b1 = (size_t)(bb * SS + row0g + 8) * HH + col;
        *(float2*)&g_ctx[b0] = make_float2(o[nf][0] * i0, o[nf][1] * i0);
        *(float2*)&g_ctx[b1] = make_float2(o[nf][2] * i1, o[nf][3] * i1);
    }
}

// ---------------------------------------------------------------------------
extern "C" void kernel_launch(void* const* d_in, const int* in_sizes, int n_in,
                              void* d_out, int out_size)
{
    const float* x     = (const float*)d_in[0];
    // d_in[1] = mask: exactly tril(ones); causal handled analytically.
    const float* W_qkv = (const float*)d_in[2];
    const float* b_qkv = (const float*)d_in[3];
    const float* W_o   = (const float*)d_in[4];
    const float* b_o   = (const float*)d_in[5];
    float* out = (float*)d_out;

    float* wt;
    cudaGetSymbolAddress((void**)&wt, g_Wt);

    static bool attrs_set = false;
    if (!attrs_set) {
        cudaFuncSetAttribute(attn_k, cudaFuncAttributeMaxDynamicSharedMemorySize, ATTN_SMEM);
        attrs_set = true;
    }

    // 1) W_qkv^T, then QKV projection (mma.sync TF32) + bias + head scatter + Q scale
    transpose_k<3072><<<dim3(96, 32), dim3(32, 8)>>>(W_qkv, wt);
    tgemm<3072, true><<<dim3(24, 32), 256>>>(x, b_qkv, nullptr);

    // 2) Causal flash attention (mma.sync TF32, 128-row Q tiles, register softmax)
    attn_k<<<dim3(16, 32), 256, ATTN_SMEM>>>();

    // 3) W_o^T, then output projection (mma.sync TF32) + bias
    transpose_k<1024><<<dim3(32, 32), dim3(32, 8)>>>(W_o, wt);
    tgemm<1024, false><<<dim3(8, 32), 256>>>(nullptr, b_o, out);
}

// round 6
// speedup vs baseline: 8.7694x; 2.4335x over previous
#include <cuda_runtime.h>
#include <cuda_fp16.h>
#include <cstdint>

#define NB 2
#define SS 2048
#define HH 1024
#define NHEAD 16
#define HD 64
#define TOK (NB*SS)

// Scratch (device globals; no runtime allocation). All fp16 pre-rounded.
__device__ __half g_X[TOK*HH];            // x rounded to half
__device__ __half g_Q[NB*NHEAD*SS*HD];    // [b,h,s,d], pre-scaled by 1/sqrt(64)
__device__ __half g_K[NB*NHEAD*SS*HD];
__device__ __half g_V[NB*NHEAD*SS*HD];
__device__ __half g_ctx[TOK*HH];          // [b*s, h]
__device__ __half g_Wt[3072*1024];        // transposed weights [N][K] (reused)

// ---------------------------------------------------------------------------
// helpers: fp16 mma m16n8k16 (fp32 acc), ldmatrix, cp.async
// ---------------------------------------------------------------------------
__device__ __forceinline__ uint32_t smem_u32(const void* p) {
    uint32_t a;
    asm("{ .reg .u64 t; cvta.to.shared.u64 t, %1; cvt.u32.u64 %0, t; }" : "=r"(a) : "l"(p));
    return a;
}
__device__ __forceinline__ void mma16(float* d, const uint32_t* a, const uint32_t* b) {
    asm volatile(
        "mma.sync.aligned.m16n8k16.row.col.f32.f16.f16.f32 "
        "{%0,%1,%2,%3}, {%4,%5,%6,%7}, {%8,%9}, {%0,%1,%2,%3};"
        : "+f"(d[0]), "+f"(d[1]), "+f"(d[2]), "+f"(d[3])
        : "r"(a[0]), "r"(a[1]), "r"(a[2]), "r"(a[3]), "r"(b[0]), "r"(b[1]));
}
__device__ __forceinline__ void ldm4(uint32_t* r, uint32_t addr) {
    asm volatile("ldmatrix.sync.aligned.m8n8.x4.shared.b16 {%0,%1,%2,%3}, [%4];"
        : "=r"(r[0]), "=r"(r[1]), "=r"(r[2]), "=r"(r[3]) : "r"(addr));
}
__device__ __forceinline__ void ldm4t(uint32_t* r, uint32_t addr) {
    asm volatile("ldmatrix.sync.aligned.m8n8.x4.trans.shared.b16 {%0,%1,%2,%3}, [%4];"
        : "=r"(r[0]), "=r"(r[1]), "=r"(r[2]), "=r"(r[3]) : "r"(addr));
}
// pack {lo, hi} floats -> f16x2 (RN)
__device__ __forceinline__ uint32_t h2(float lo, float hi) {
    uint32_t r;
    asm("cvt.rn.f16x2.f32 %0, %1, %2;" : "=r"(r) : "f"(hi), "f"(lo));
    return r;
}
#define CP16(dst, src) \
    asm volatile("cp.async.cg.shared.global [%0], [%1], 16;" :: "r"(dst), "l"(src))
#define CP_COMMIT asm volatile("cp.async.commit_group;")
#define CP_WAIT(n) asm volatile("cp.async.wait_group %0;" :: "n"(n))

// ---------------------------------------------------------------------------
// x -> half
// ---------------------------------------------------------------------------
__global__ void conv_x(const float4* __restrict__ x)
{
    const int i = blockIdx.x * 256 + threadIdx.x;   // 1M float4
    float4 v = x[i];
    __half2* o = (__half2*)g_X;
    o[2*i]   = __floats2half2_rn(v.x, v.y);
    o[2*i+1] = __floats2half2_rn(v.z, v.w);
}

// ---------------------------------------------------------------------------
// Weight transpose: Wt[n][k] = half(W[k][n])
// ---------------------------------------------------------------------------
template<int N>
__global__ void transpose_k(const float* __restrict__ W)
{
    __shared__ float t[32][33];
    const int x = threadIdx.x, y = threadIdx.y;
    const int n0 = blockIdx.x * 32, k0 = blockIdx.y * 32;
    #pragma unroll
    for (int j = 0; j < 32; j += 8)
        t[y + j][x] = W[(size_t)(k0 + y + j) * N + n0 + x];
    __syncthreads();
    #pragma unroll
    for (int j = 0; j < 32; j += 8)
        g_Wt[(size_t)(n0 + y + j) * 1024 + k0 + x] = __float2half_rn(t[x][y + j]);
}

// ---------------------------------------------------------------------------
// FP16 mma GEMM: D[4096, NTOT] = A[4096,1024] x Wt^T + bias
// CTA 128x128, KC=64, 2-stage cp.async double buffer, 8 warps (2m x 4n),
// warp tile 64x32, XOR-swizzled smem (128B rows), ldmatrix fragments.
// ---------------------------------------------------------------------------
template<int NTOT, bool QKV>
__global__ __launch_bounds__(256, 2) void tgemm(const float* __restrict__ bias,
                                                float* __restrict__ out)
{
    extern __shared__ char smem[];   // 2 stages x (A 16KB + B 16KB) = 64KB
    const uint32_t sbase = smem_u32(smem);
    const int tid = threadIdx.x, lane = tid & 31, warp = tid >> 5;
    const int g = lane >> 2, t = lane & 3;
    const int q = lane >> 3, rr = lane & 7;
    const int wm = warp >> 2, wn = warp & 3;
    const int m0 = blockIdx.y * 128;
    const int n0 = blockIdx.x * 128;
    const __half* __restrict__ Ap = QKV ? (const __half*)g_X : (const __half*)g_ctx;
    const __half* __restrict__ Bp = (const __half*)g_Wt;

    // cp.async issue for one stage: A 128x64, B 128x64 halves (8 units/row)
    auto issue = [&](int it, int st) {
        const uint32_t Ad = sbase + st * 32768;
        const uint32_t Bd = Ad + 16384;
        const int kb = it * 64;
        #pragma unroll
        for (int j = 0; j < 4; j++) {
            const int idx = tid + 256 * j;
            const int r = idx >> 3, u = idx & 7;
            const uint32_t sw = (uint32_t)r * 128 + ((u ^ (r & 7)) << 4);
            CP16(Ad + sw, Ap + (size_t)(m0 + r) * 1024 + kb + u * 8);
            CP16(Bd + sw, Bp + (size_t)(n0 + r) * 1024 + kb + u * 8);
        }
        CP_COMMIT;
    };

    float acc[4][4][4];
    #pragma unroll
    for (int mf = 0; mf < 4; mf++)
        #pragma unroll
        for (int nf = 0; nf < 4; nf++)
            #pragma unroll
            for (int c = 0; c < 4; c++) acc[mf][nf][c] = 0.0f;

    issue(0, 0);

    for (int it = 0; it < 16; ++it) {
        __syncthreads();                 // all warps done reading buf[(it+1)&1]
        if (it < 15) { issue(it + 1, (it + 1) & 1); CP_WAIT(1); }
        else         { CP_WAIT(0); }
        __syncthreads();                 // stage it fully visible

        const uint32_t As = sbase + (it & 1) * 32768;
        const uint32_t Bs = As + 16384;
        #pragma unroll
        for (int ks = 0; ks < 4; ks++) {
            uint32_t af[4][4], bf[2][4];
            #pragma unroll
            for (int mf = 0; mf < 4; mf++) {
                const int row = wm*64 + mf*16 + ((q & 1) << 3) + rr;
                const int u = 2*ks + (q >> 1);
                ldm4(af[mf], As + row * 128 + ((u ^ rr) << 4));
            }
            #pragma unroll
            for (int p = 0; p < 2; p++) {
                const int row = wn*32 + p*16 + ((q >> 1) << 3) + rr;
                const int u = 2*ks + (q & 1);
                ldm4(bf[p], Bs + row * 128 + ((u ^ rr) << 4));
            }
            #pragma unroll
            for (int mf = 0; mf < 4; mf++) {
                mma16(acc[mf][0], af[mf], &bf[0][0]);
                mma16(acc[mf][1], af[mf], &bf[0][2]);
                mma16(acc[mf][2], af[mf], &bf[1][0]);
                mma16(acc[mf][3], af[mf], &bf[1][2]);
            }
        }
    }

    // Epilogue
    #pragma unroll
    for (int nf = 0; nf < 4; nf++) {
        const int col = n0 + wn*32 + nf*8 + 2*t;   // even
        const float b0 = bias[col], b1 = bias[col + 1];
        if (QKV) {
            const int which = col >> 10;
            const int c = col & 1023;
            const int head = c >> 6, d0 = c & 63;
            const float scale = (which == 0) ? 0.125f : 1.0f;
            __half* dst = (which == 0) ? (__half*)g_Q : (which == 1) ? (__half*)g_K : (__half*)g_V;
            #pragma unroll
            for (int mf = 0; mf < 4; mf++) {
                #pragma unroll
                for (int h = 0; h < 2; h++) {
                    const int row = m0 + wm*64 + mf*16 + g + h*8;
                    const int b_ = row >> 11, s_ = row & 2047;
                    const size_t idx = ((size_t)(b_ * NHEAD + head) * SS + s_) * HD + d0;
                    *(uint32_t*)&dst[idx] = h2((acc[mf][nf][2*h]   + b0) * scale,
                                               (acc[mf][nf][2*h+1] + b1) * scale);
                }
            }
        } else {
            #pragma unroll
            for (int mf = 0; mf < 4; mf++) {
                #pragma unroll
                for (int h = 0; h < 2; h++) {
                    const int row = m0 + wm*64 + mf*16 + g + h*8;
                    float2 v;
                    v.x = acc[mf][nf][2*h]   + b0;
                    v.y = acc[mf][nf][2*h+1] + b1;
                    *(float2*)&out[(size_t)row * 1024 + col] = v;
                }
            }
        }
    }
}

// ---------------------------------------------------------------------------
// Causal flash attention v3 (fp16 mma): Q-tile 128 x K-tile 64, 8 warps.
// Q fragments in registers (loaded once). P stays in registers (S C-frag ->
// PV A-frag repack). K/V double-buffered cp.async. 2 syncs/iter.
// ---------------------------------------------------------------------------
__global__ __launch_bounds__(256, 2) void attn_k()
{
    __shared__ char smem[32768];  // 2 stages x (K 8KB + V 8KB)
    const uint32_t sbase = smem_u32(smem);
    const int bh = blockIdx.y;
    const int qt = (int)gridDim.x - 1 - (int)blockIdx.x;  // heavy tiles first
    const int q0 = qt * 128;
    const __half* __restrict__ Qg = (const __half*)g_Q + (size_t)bh * SS * HD + (size_t)q0 * HD;
    const __half* __restrict__ Kg = (const __half*)g_K + (size_t)bh * SS * HD;
    const __half* __restrict__ Vg = (const __half*)g_V + (size_t)bh * SS * HD;
    const int tid = threadIdx.x, lane = tid & 31, warp = tid >> 5;
    const int g = lane >> 2, t = lane & 3;
    const int q = lane >> 3, rr = lane & 7;

    auto issue = [&](int kt, int st) {
        const uint32_t Kd = sbase + st * 16384;
        const uint32_t Vd = Kd + 8192;
        const __half* Ks = Kg + (size_t)kt * 64 * HD;
        const __half* Vs = Vg + (size_t)kt * 64 * HD;
        #pragma unroll
        for (int j = 0; j < 2; j++) {
            const int idx = tid + 256 * j;
            const int r = idx >> 3, u = idx & 7;
            const uint32_t sw = (uint32_t)r * 128 + ((u ^ (r & 7)) << 4);
            CP16(Kd + sw, Ks + r * 64 + u * 8);
            CP16(Vd + sw, Vs + r * 64 + u * 8);
        }
        CP_COMMIT;
    };

    // Q fragments: warp rows warp*16 + {g, g+8}, 4 k16-chunks
    uint32_t qf[4][4];
    {
        const __half* Qr = Qg + (size_t)(warp*16 + g) * 64;
        #pragma unroll
        for (int ks = 0; ks < 4; ks++) {
            qf[ks][0] = *(const uint32_t*)(Qr + ks*16 + 2*t);
            qf[ks][1] = *(const uint32_t*)(Qr + 8*64 + ks*16 + 2*t);
            qf[ks][2] = *(const uint32_t*)(Qr + ks*16 + 8 + 2*t);
            qf[ks][3] = *(const uint32_t*)(Qr + 8*64 + ks*16 + 8 + 2*t);
        }
    }

    float o[8][4];
    #pragma unroll
    for (int nf = 0; nf < 8; nf++)
        #pragma unroll
        for (int c = 0; c < 4; c++) o[nf][c] = 0.0f;
    float mr0 = -1e30f, mr1 = -1e30f, l0 = 0.0f, l1 = 0.0f;

    const int ktmax = 2*qt + 1;
    const int row0g = q0 + warp*16 + g;

    issue(0, 0);

    for (int kt = 0; kt <= ktmax; kt++) {
        __syncthreads();
        if (kt < ktmax) { issue(kt + 1, (kt + 1) & 1); CP_WAIT(1); }
        else            { CP_WAIT(0); }
        __syncthreads();

        const uint32_t Kst = sbase + (kt & 1) * 16384;
        const uint32_t Vst = Kst + 8192;
        const bool act = (kt*64 <= q0 + warp*16 + 15);
        if (!act) continue;   // no smem writes below; syncs stay aligned (top-of-loop only)

        // ---- S = Q K^T ----
        float sc[8][4];
        #pragma unroll
        for (int nf = 0; nf < 8; nf++)
            #pragma unroll
            for (int c = 0; c < 4; c++) sc[nf][c] = 0.0f;
        #pragma unroll
        for (int ks = 0; ks < 4; ks++) {
            #pragma unroll
            for (int np = 0; np < 4; np++) {
                uint32_t kb[4];
                const int row = np*16 + ((q >> 1) << 3) + rr;
                const int u = 2*ks + (q & 1);
                ldm4(kb, Kst + row * 128 + ((u ^ rr) << 4));
                mma16(sc[2*np],   qf[ks], &kb[0]);
                mma16(sc[2*np+1], qf[ks], &kb[2]);
            }
        }
        // ---- causal mask (last two key tiles only) ----
        if (kt >= 2*qt) {
            #pragma unroll
            for (int nf = 0; nf < 8; nf++) {
                const int key = kt*64 + nf*8 + 2*t;
                if (key     > row0g)     sc[nf][0] = -1e30f;
                if (key + 1 > row0g)     sc[nf][1] = -1e30f;
                if (key     > row0g + 8) sc[nf][2] = -1e30f;
                if (key + 1 > row0g + 8) sc[nf][3] = -1e30f;
            }
        }
        // ---- register online softmax (rows g, g+8; quad reduce) ----
        float mx0 = -1e30f, mx1 = -1e30f;
        #pragma unroll
        for (int nf = 0; nf < 8; nf++) {
            mx0 = fmaxf(mx0, fmaxf(sc[nf][0], sc[nf][1]));
            mx1 = fmaxf(mx1, fmaxf(sc[nf][2], sc[nf][3]));
        }
        mx0 = fmaxf(mx0, __shfl_xor_sync(0xffffffffu, mx0, 1));
        mx0 = fmaxf(mx0, __shfl_xor_sync(0xffffffffu, mx0, 2));
        mx1 = fmaxf(mx1, __shfl_xor_sync(0xffffffffu, mx1, 1));
        mx1 = fmaxf(mx1, __shfl_xor_sync(0xffffffffu, mx1, 2));
        const float nm0 = fmaxf(mr0, mx0);
        const float nm1 = fmaxf(mr1, mx1);
        const float c0 = __expf(mr0 - nm0);
        const float c1 = __expf(mr1 - nm1);
        mr0 = nm0; mr1 = nm1;
        float s0 = 0.0f, s1 = 0.0f;
        #pragma unroll
        for (int nf = 0; nf < 8; nf++) {
            sc[nf][0] = __expf(sc[nf][0] - nm0); s0 += sc[nf][0];
            sc[nf][1] = __expf(sc[nf][1] - nm0); s0 += sc[nf][1];
            sc[nf][2] = __expf(sc[nf][2] - nm1); s1 += sc[nf][2];
            sc[nf][3] = __expf(sc[nf][3] - nm1); s1 += sc[nf][3];
        }
        s0 += __shfl_xor_sync(0xffffffffu, s0, 1);
        s0 += __shfl_xor_sync(0xffffffffu, s0, 2);
        s1 += __shfl_xor_sync(0xffffffffu, s1, 1);
        s1 += __shfl_xor_sync(0xffffffffu, s1, 2);
        l0 = l0 * c0 + s0;
        l1 = l1 * c1 + s1;
        #pragma unroll
        for (int nf = 0; nf < 8; nf++) {
            o[nf][0] *= c0; o[nf][1] *= c0;
            o[nf][2] *= c1; o[nf][3] *= c1;
        }
        // ---- P (registers) -> PV A-fragments; O += P V ----
        #pragma unroll
        for (int ks = 0; ks < 4; ks++) {
            uint32_t pa[4];
            pa[0] = h2(sc[2*ks][0],   sc[2*ks][1]);
            pa[1] = h2(sc[2*ks][2],   sc[2*ks][3]);
            pa[2] = h2(sc[2*ks+1][0], sc[2*ks+1][1]);
            pa[3] = h2(sc[2*ks+1][2], sc[2*ks+1][3]);
            #pragma unroll
            for (int np = 0; np < 4; np++) {
                uint32_t vb[4];
                const int row = 16*ks + ((q & 1) << 3) + rr;
                const int u = 2*np + (q >> 1);
                ldm4t(vb, Vst + row * 128 + ((u ^ rr) << 4));
                mma16(o[2*np],   pa, &vb[0]);
                mma16(o[2*np+1], pa, &vb[2]);
            }
        }
    }

    // ---- epilogue: ctx as half ----
    const float i0 = 1.0f / l0, i1 = 1.0f / l1;
    const int bb = bh >> 4, hh = bh & 15;
    __half* ctx = (__half*)g_ctx;
    #pragma unroll
    for (int nf = 0; nf < 8; nf++) {
        const int col = hh*64 + nf*8 + 2*t;
        const size_t b0 = (size_t)(bb * SS + row0g) * HH + col;
        const size_t b1 = (size_t)(bb * SS + row0g + 8) * HH + col;
        *(uint32_t*)&ctx[b0] = h2(o[nf][0] * i0, o[nf][1] * i0);
        *(uint32_t*)&ctx[b1] = h2(o[nf][2] * i1, o[nf][3] * i1);
    }
}

// ---------------------------------------------------------------------------
extern "C" void kernel_launch(void* const* d_in, const int* in_sizes, int n_in,
                              void* d_out, int out_size)
{
    const float* x     = (const float*)d_in[0];
    // d_in[1] = mask: exactly tril(ones); causal handled analytically.
    const float* W_qkv = (const float*)d_in[2];
    const float* b_qkv = (const float*)d_in[3];
    const float* W_o   = (const float*)d_in[4];
    const float* b_o   = (const float*)d_in[5];
    float* out = (float*)d_out;

    static bool attrs_set = false;
    if (!attrs_set) {
        cudaFuncSetAttribute(tgemm<3072, true>,  cudaFuncAttributeMaxDynamicSharedMemorySize, 65536);
        cudaFuncSetAttribute(tgemm<1024, false>, cudaFuncAttributeMaxDynamicSharedMemorySize, 65536);
        attrs_set = true;
    }

    // 0) round x to fp16
    conv_x<<<4096, 256>>>((const float4*)x);

    // 1) W_qkv^T (half), then QKV projection + bias + head scatter + Q scale
    transpose_k<3072><<<dim3(96, 32), dim3(32, 8)>>>(W_qkv);
    tgemm<3072, true><<<dim3(24, 32), 256, 65536>>>(b_qkv, nullptr);

    // 2) Causal flash attention (fp16 mma, register P)
    attn_k<<<dim3(16, 32), 256>>>();

    // 3) W_o^T (half), then output projection + bias (fp32 out)
    transpose_k<1024><<<dim3(32, 32), dim3(32, 8)>>>(W_o);
    tgemm<1024, false><<<dim3(8, 32), 256, 65536>>>(b_o, out);
}

// round 7
// speedup vs baseline: 9.3492x; 1.0661x over previous
#include <cuda_runtime.h>
#include <cuda_fp16.h>
#include <cstdint>

#define NB 2
#define SS 2048
#define HH 1024
#define NHEAD 16
#define HD 64
#define TOK (NB*SS)

// Scratch (device globals; no runtime allocation). All fp16 pre-rounded.
__device__ __half g_X[TOK*HH];            // x rounded to half
__device__ __half g_Q[NB*NHEAD*SS*HD];    // [b,h,s,d], pre-scaled by log2e/sqrt(64)
__device__ __half g_K[NB*NHEAD*SS*HD];
__device__ __half g_V[NB*NHEAD*SS*HD];
__device__ __half g_ctx[TOK*HH];          // [b*s, h]
__device__ __half g_Wt[3072*1024];        // transposed weights [N][K] (reused)

// ---------------------------------------------------------------------------
// helpers: fp16 mma m16n8k16 (fp32 acc), ldmatrix, cp.async
// ---------------------------------------------------------------------------
__device__ __forceinline__ uint32_t smem_u32(const void* p) {
    uint32_t a;
    asm("{ .reg .u64 t; cvta.to.shared.u64 t, %1; cvt.u32.u64 %0, t; }" : "=r"(a) : "l"(p));
    return a;
}
__device__ __forceinline__ void mma16(float* d, const uint32_t* a, const uint32_t* b) {
    asm volatile(
        "mma.sync.aligned.m16n8k16.row.col.f32.f16.f16.f32 "
        "{%0,%1,%2,%3}, {%4,%5,%6,%7}, {%8,%9}, {%0,%1,%2,%3};"
        : "+f"(d[0]), "+f"(d[1]), "+f"(d[2]), "+f"(d[3])
        : "r"(a[0]), "r"(a[1]), "r"(a[2]), "r"(a[3]), "r"(b[0]), "r"(b[1]));
}
__device__ __forceinline__ void ldm4(uint32_t* r, uint32_t addr) {
    asm volatile("ldmatrix.sync.aligned.m8n8.x4.shared.b16 {%0,%1,%2,%3}, [%4];"
        : "=r"(r[0]), "=r"(r[1]), "=r"(r[2]), "=r"(r[3]) : "r"(addr));
}
__device__ __forceinline__ void ldm4t(uint32_t* r, uint32_t addr) {
    asm volatile("ldmatrix.sync.aligned.m8n8.x4.trans.shared.b16 {%0,%1,%2,%3}, [%4];"
        : "=r"(r[0]), "=r"(r[1]), "=r"(r[2]), "=r"(r[3]) : "r"(addr));
}
// pack {lo, hi} floats -> f16x2 (RN)
__device__ __forceinline__ uint32_t h2(float lo, float hi) {
    uint32_t r;
    asm("cvt.rn.f16x2.f32 %0, %1, %2;" : "=r"(r) : "f"(hi), "f"(lo));
    return r;
}
// dual-half exp2
__device__ __forceinline__ uint32_t ex2h2(uint32_t x) {
    uint32_t r;
    asm("ex2.approx.f16x2 %0, %1;" : "=r"(r) : "r"(x));
    return r;
}
__device__ __forceinline__ float ex2f(float x) {
    float r;
    asm("ex2.approx.f32 %0, %1;" : "=f"(r) : "f"(x));
    return r;
}
#define CP16(dst, src) \
    asm volatile("cp.async.cg.shared.global [%0], [%1], 16;" :: "r"(dst), "l"(src))
#define CP_COMMIT asm volatile("cp.async.commit_group;")
#define CP_WAIT(n) asm volatile("cp.async.wait_group %0;" :: "n"(n))

// ---------------------------------------------------------------------------
// x -> half
// ---------------------------------------------------------------------------
__global__ void conv_x(const float4* __restrict__ x)
{
    const int i = blockIdx.x * 256 + threadIdx.x;   // 1M float4
    float4 v = x[i];
    __half2* o = (__half2*)g_X;
    o[2*i]   = __floats2half2_rn(v.x, v.y);
    o[2*i+1] = __floats2half2_rn(v.z, v.w);
}

// ---------------------------------------------------------------------------
// Weight transpose: Wt[n][k] = half(W[k][n])
// ---------------------------------------------------------------------------
template<int N>
__global__ void transpose_k(const float* __restrict__ W)
{
    __shared__ float t[32][33];
    const int x = threadIdx.x, y = threadIdx.y;
    const int n0 = blockIdx.x * 32, k0 = blockIdx.y * 32;
    #pragma unroll
    for (int j = 0; j < 32; j += 8)
        t[y + j][x] = W[(size_t)(k0 + y + j) * N + n0 + x];
    __syncthreads();
    #pragma unroll
    for (int j = 0; j < 32; j += 8)
        g_Wt[(size_t)(n0 + y + j) * 1024 + k0 + x] = __float2half_rn(t[x][y + j]);
}

// ---------------------------------------------------------------------------
// FP16 mma GEMM: D[4096, NTOT] = A[4096,1024] x Wt^T + bias
// CTA 128x128, KC=64, 2-stage cp.async double buffer, 8 warps (2m x 4n),
// warp tile 64x32, XOR-swizzled smem (128B rows), ldmatrix fragments.
// ---------------------------------------------------------------------------
template<int NTOT, bool QKV>
__global__ __launch_bounds__(256, 2) void tgemm(const float* __restrict__ bias,
                                                float* __restrict__ out)
{
    extern __shared__ char smem[];   // 2 stages x (A 16KB + B 16KB) = 64KB
    const uint32_t sbase = smem_u32(smem);
    const int tid = threadIdx.x, lane = tid & 31, warp = tid >> 5;
    const int g = lane >> 2, t = lane & 3;
    const int q = lane >> 3, rr = lane & 7;
    const int wm = warp >> 2, wn = warp & 3;
    const int m0 = blockIdx.y * 128;
    const int n0 = blockIdx.x * 128;
    const __half* __restrict__ Ap = QKV ? (const __half*)g_X : (const __half*)g_ctx;
    const __half* __restrict__ Bp = (const __half*)g_Wt;

    auto issue = [&](int it, int st) {
        const uint32_t Ad = sbase + st * 32768;
        const uint32_t Bd = Ad + 16384;
        const int kb = it * 64;
        #pragma unroll
        for (int j = 0; j < 4; j++) {
            const int idx = tid + 256 * j;
            const int r = idx >> 3, u = idx & 7;
            const uint32_t sw = (uint32_t)r * 128 + ((u ^ (r & 7)) << 4);
            CP16(Ad + sw, Ap + (size_t)(m0 + r) * 1024 + kb + u * 8);
            CP16(Bd + sw, Bp + (size_t)(n0 + r) * 1024 + kb + u * 8);
        }
        CP_COMMIT;
    };

    float acc[4][4][4];
    #pragma unroll
    for (int mf = 0; mf < 4; mf++)
        #pragma unroll
        for (int nf = 0; nf < 4; nf++)
            #pragma unroll
            for (int c = 0; c < 4; c++) acc[mf][nf][c] = 0.0f;

    issue(0, 0);

    for (int it = 0; it < 16; ++it) {
        __syncthreads();
        if (it < 15) { issue(it + 1, (it + 1) & 1); CP_WAIT(1); }
        else         { CP_WAIT(0); }
        __syncthreads();

        const uint32_t As = sbase + (it & 1) * 32768;
        const uint32_t Bs = As + 16384;
        #pragma unroll
        for (int ks = 0; ks < 4; ks++) {
            uint32_t af[4][4], bf[2][4];
            #pragma unroll
            for (int mf = 0; mf < 4; mf++) {
                const int row = wm*64 + mf*16 + ((q & 1) << 3) + rr;
                const int u = 2*ks + (q >> 1);
                ldm4(af[mf], As + row * 128 + ((u ^ rr) << 4));
            }
            #pragma unroll
            for (int p = 0; p < 2; p++) {
                const int row = wn*32 + p*16 + ((q >> 1) << 3) + rr;
                const int u = 2*ks + (q & 1);
                ldm4(bf[p], Bs + row * 128 + ((u ^ rr) << 4));
            }
            #pragma unroll
            for (int mf = 0; mf < 4; mf++) {
                mma16(acc[mf][0], af[mf], &bf[0][0]);
                mma16(acc[mf][1], af[mf], &bf[0][2]);
                mma16(acc[mf][2], af[mf], &bf[1][0]);
                mma16(acc[mf][3], af[mf], &bf[1][2]);
            }
        }
    }

    // Epilogue
    #pragma unroll
    for (int nf = 0; nf < 4; nf++) {
        const int col = n0 + wn*32 + nf*8 + 2*t;   // even
        const float b0 = bias[col], b1 = bias[col + 1];
        if (QKV) {
            const int which = col >> 10;
            const int c = col & 1023;
            const int head = c >> 6, d0 = c & 63;
            // Q pre-scale: 1/sqrt(64) * log2(e)  (softmax runs in exp2 domain)
            const float scale = (which == 0) ? 0.125f * 1.44269504f : 1.0f;
            __half* dst = (which == 0) ? (__half*)g_Q : (which == 1) ? (__half*)g_K : (__half*)g_V;
            #pragma unroll
            for (int mf = 0; mf < 4; mf++) {
                #pragma unroll
                for (int h = 0; h < 2; h++) {
                    const int row = m0 + wm*64 + mf*16 + g + h*8;
                    const int b_ = row >> 11, s_ = row & 2047;
                    const size_t idx = ((size_t)(b_ * NHEAD + head) * SS + s_) * HD + d0;
                    *(uint32_t*)&dst[idx] = h2((acc[mf][nf][2*h]   + b0) * scale,
                                               (acc[mf][nf][2*h+1] + b1) * scale);
                }
            }
        } else {
            #pragma unroll
            for (int mf = 0; mf < 4; mf++) {
                #pragma unroll
                for (int h = 0; h < 2; h++) {
                    const int row = m0 + wm*64 + mf*16 + g + h*8;
                    float2 v;
                    v.x = acc[mf][nf][2*h]   + b0;
                    v.y = acc[mf][nf][2*h+1] + b1;
                    *(float2*)&out[(size_t)row * 1024 + col] = v;
                }
            }
        }
    }
}

// ---------------------------------------------------------------------------
// Causal flash attention v4 (fp16 mma, log2-domain softmax):
// Q-tile 128 x K-tile 64, 8 warps. Q frags in registers. P never touches
// smem: (s-m) packed f16x2 -> ex2.approx.f16x2 -> PV A-frags directly.
// Row sums via ones-column MMA on the tensor pipe. 2 syncs/iter.
// ---------------------------------------------------------------------------
__global__ __launch_bounds__(256, 2) void attn_k()
{
    __shared__ char smem[32768];  // 2 stages x (K 8KB + V 8KB)
    const uint32_t sbase = smem_u32(smem);
    const int bh = blockIdx.y;
    const int qt = (int)gridDim.x - 1 - (int)blockIdx.x;  // heavy tiles first
    const int q0 = qt * 128;
    const __half* __restrict__ Qg = (const __half*)g_Q + (size_t)bh * SS * HD + (size_t)q0 * HD;
    const __half* __restrict__ Kg = (const __half*)g_K + (size_t)bh * SS * HD;
    const __half* __restrict__ Vg = (const __half*)g_V + (size_t)bh * SS * HD;
    const int tid = threadIdx.x, lane = tid & 31, warp = tid >> 5;
    const int g = lane >> 2, t = lane & 3;
    const int q = lane >> 3, rr = lane & 7;

    auto issue = [&](int kt, int st) {
        const uint32_t Kd = sbase + st * 16384;
        const uint32_t Vd = Kd + 8192;
        const __half* Ks = Kg + (size_t)kt * 64 * HD;
        const __half* Vs = Vg + (size_t)kt * 64 * HD;
        #pragma unroll
        for (int j = 0; j < 2; j++) {
            const int idx = tid + 256 * j;
            const int r = idx >> 3, u = idx & 7;
            const uint32_t sw = (uint32_t)r * 128 + ((u ^ (r & 7)) << 4);
            CP16(Kd + sw, Ks + r * 64 + u * 8);
            CP16(Vd + sw, Vs + r * 64 + u * 8);
        }
        CP_COMMIT;
    };

    // Q fragments: warp rows warp*16 + {g, g+8}, 4 k16-chunks
    uint32_t qf[4][4];
    {
        const __half* Qr = Qg + (size_t)(warp*16 + g) * 64;
        #pragma unroll
        for (int ks = 0; ks < 4; ks++) {
            qf[ks][0] = *(const uint32_t*)(Qr + ks*16 + 2*t);
            qf[ks][1] = *(const uint32_t*)(Qr + 8*64 + ks*16 + 2*t);
            qf[ks][2] = *(const uint32_t*)(Qr + ks*16 + 8 + 2*t);
            qf[ks][3] = *(const uint32_t*)(Qr + 8*64 + ks*16 + 8 + 2*t);
        }
    }

    float o[8][4];
    #pragma unroll
    for (int nf = 0; nf < 8; nf++)
        #pragma unroll
        for (int c = 0; c < 4; c++) o[nf][c] = 0.0f;
    float mr0 = -1e30f, mr1 = -1e30f, l0 = 0.0f, l1 = 0.0f;

    const int ktmax = 2*qt + 1;
    const int row0g = q0 + warp*16 + g;
    const uint32_t onesb[2] = { 0x3C003C00u, 0x3C003C00u };  // fp16 {1,1}

    issue(0, 0);

    for (int kt = 0; kt <= ktmax; kt++) {
        __syncthreads();
        if (kt < ktmax) { issue(kt + 1, (kt + 1) & 1); CP_WAIT(1); }
        else            { CP_WAIT(0); }
        __syncthreads();

        const uint32_t Kst = sbase + (kt & 1) * 16384;
        const uint32_t Vst = Kst + 8192;
        const bool act = (kt*64 <= q0 + warp*16 + 15);
        if (!act) continue;   // no smem writes below; syncs stay aligned

        // ---- S = Q K^T (log2 domain, scale folded into Q) ----
        float sc[8][4];
        #pragma unroll
        for (int nf = 0; nf < 8; nf++)
            #pragma unroll
            for (int c = 0; c < 4; c++) sc[nf][c] = 0.0f;
        #pragma unroll
        for (int ks = 0; ks < 4; ks++) {
            #pragma unroll
            for (int np = 0; np < 4; np++) {
                uint32_t kb[4];
                const int row = np*16 + ((q >> 1) << 3) + rr;
                const int u = 2*ks + (q & 1);
                ldm4(kb, Kst + row * 128 + ((u ^ rr) << 4));
                mma16(sc[2*np],   qf[ks], &kb[0]);
                mma16(sc[2*np+1], qf[ks], &kb[2]);
            }
        }
        // ---- causal mask (last two key tiles only) ----
        if (kt >= 2*qt) {
            #pragma unroll
            for (int nf = 0; nf < 8; nf++) {
                const int key = kt*64 + nf*8 + 2*t;
                if (key     > row0g)     sc[nf][0] = -1e30f;
                if (key + 1 > row0g)     sc[nf][1] = -1e30f;
                if (key     > row0g + 8) sc[nf][2] = -1e30f;
                if (key + 1 > row0g + 8) sc[nf][3] = -1e30f;
            }
        }
        // ---- online max (rows g, g+8; quad reduce) ----
        float mx0 = -1e30f, mx1 = -1e30f;
        #pragma unroll
        for (int nf = 0; nf < 8; nf++) {
            mx0 = fmaxf(mx0, fmaxf(sc[nf][0], sc[nf][1]));
            mx1 = fmaxf(mx1, fmaxf(sc[nf][2], sc[nf][3]));
        }
        mx0 = fmaxf(mx0, __shfl_xor_sync(0xffffffffu, mx0, 1));
        mx0 = fmaxf(mx0, __shfl_xor_sync(0xffffffffu, mx0, 2));
        mx1 = fmaxf(mx1, __shfl_xor_sync(0xffffffffu, mx1, 1));
        mx1 = fmaxf(mx1, __shfl_xor_sync(0xffffffffu, mx1, 2));
        const float nm0 = fmaxf(mr0, mx0);
        const float nm1 = fmaxf(mr1, mx1);
        const float c0 = ex2f(mr0 - nm0);
        const float c1 = ex2f(mr1 - nm1);
        mr0 = nm0; mr1 = nm1;
        #pragma unroll
        for (int nf = 0; nf < 8; nf++) {
            o[nf][0] *= c0; o[nf][1] *= c0;
            o[nf][2] *= c1; o[nf][3] *= c1;
        }
        // ---- P = exp2(s - m) directly into fp16 A-fragments ----
        uint32_t pa[4][4];
        #pragma unroll
        for (int ks = 0; ks < 4; ks++) {
            pa[ks][0] = ex2h2(h2(sc[2*ks][0]   - nm0, sc[2*ks][1]   - nm0));
            pa[ks][1] = ex2h2(h2(sc[2*ks][2]   - nm1, sc[2*ks][3]   - nm1));
            pa[ks][2] = ex2h2(h2(sc[2*ks+1][0] - nm0, sc[2*ks+1][1] - nm0));
            pa[ks][3] = ex2h2(h2(sc[2*ks+1][2] - nm1, sc[2*ks+1][3] - nm1));
        }
        // ---- O += P V;  row sums via ones-column mma ----
        float ls[4] = { 0.0f, 0.0f, 0.0f, 0.0f };
        #pragma unroll
        for (int ks = 0; ks < 4; ks++) {
            mma16(ls, pa[ks], onesb);
            #pragma unroll
            for (int np = 0; np < 4; np++) {
                uint32_t vb[4];
                const int row = 16*ks + ((q & 1) << 3) + rr;
                const int u = 2*np + (q >> 1);
                ldm4t(vb, Vst + row * 128 + ((u ^ rr) << 4));
                mma16(o[2*np],   pa[ks], &vb[0]);
                mma16(o[2*np+1], pa[ks], &vb[2]);
            }
        }
        l0 = l0 * c0 + ls[0];
        l1 = l1 * c1 + ls[2];
    }

    // ---- epilogue: ctx as half ----
    const float i0 = 1.0f / l0, i1 = 1.0f / l1;
    const int bb = bh >> 4, hh = bh & 15;
    __half* ctx = (__half*)g_ctx;
    #pragma unroll
    for (int nf = 0; nf < 8; nf++) {
        const int col = hh*64 + nf*8 + 2*t;
        const size_t b0 = (size_t)(bb * SS + row0g) * HH + col;
        const size_t b1 = (size_t)(bb * SS + row0g + 8) * HH + col;
        *(uint32_t*)&ctx[b0] = h2(o[nf][0] * i0, o[nf][1] * i0);
        *(uint32_t*)&ctx[b1] = h2(o[nf][2] * i1, o[nf][3] * i1);
    }
}

// ---------------------------------------------------------------------------
extern "C" void kernel_launch(void* const* d_in, const int* in_sizes, int n_in,
                              void* d_out, int out_size)
{
    const float* x     = (const float*)d_in[0];
    // d_in[1] = mask: exactly tril(ones); causal handled analytically.
    const float* W_qkv = (const float*)d_in[2];
    const float* b_qkv = (const float*)d_in[3];
    const float* W_o   = (const float*)d_in[4];
    const float* b_o   = (const float*)d_in[5];
    float* out = (float*)d_out;

    static bool attrs_set = false;
    if (!attrs_set) {
        cudaFuncSetAttribute(tgemm<3072, true>,  cudaFuncAttributeMaxDynamicSharedMemorySize, 65536);
        cudaFuncSetAttribute(tgemm<1024, false>, cudaFuncAttributeMaxDynamicSharedMemorySize, 65536);
        attrs_set = true;
    }

    // 0) round x to fp16
    conv_x<<<4096, 256>>>((const float4*)x);

    // 1) W_qkv^T (half), then QKV projection + bias + head scatter + Q scale
    transpose_k<3072><<<dim3(96, 32), dim3(32, 8)>>>(W_qkv);
    tgemm<3072, true><<<dim3(24, 32), 256, 65536>>>(b_qkv, nullptr);

    // 2) Causal flash attention (fp16 mma, register P, exp2-domain softmax)
    attn_k<<<dim3(16, 32), 256>>>();

    // 3) W_o^T (half), then output projection + bias (fp32 out)
    transpose_k<1024><<<dim3(32, 32), dim3(32, 8)>>>(W_o);
    tgemm<1024, false><<<dim3(8, 32), 256, 65536>>>(b_o, out);
}

// round 8
// speedup vs baseline: 10.1944x; 1.0904x over previous
#include <cuda_runtime.h>
#include <cuda_fp16.h>
#include <cstdint>

#define NB 2
#define SS 2048
#define HH 1024
#define NHEAD 16
#define HD 64
#define TOK (NB*SS)

// Scratch (device globals; no runtime allocation). All fp16 pre-rounded.
__device__ __half g_X[TOK*HH];            // x rounded to half
__device__ __half g_Q[NB*NHEAD*SS*HD];    // [b,h,s,d], pre-scaled by log2e/sqrt(64)
__device__ __half g_K[NB*NHEAD*SS*HD];
__device__ __half g_V[NB*NHEAD*SS*HD];
__device__ __half g_ctx[TOK*HH];          // [b*s, h]
__device__ __half g_Wt[3072*1024];        // transposed weights [N][K] (reused)

// ---------------------------------------------------------------------------
// helpers: fp16 mma m16n8k16 (fp32 acc), ldmatrix, cp.async
// ---------------------------------------------------------------------------
__device__ __forceinline__ uint32_t smem_u32(const void* p) {
    uint32_t a;
    asm("{ .reg .u64 t; cvta.to.shared.u64 t, %1; cvt.u32.u64 %0, t; }" : "=r"(a) : "l"(p));
    return a;
}
// pure register op — non-volatile so the compiler can schedule freely
__device__ __forceinline__ void mma16(float* d, const uint32_t* a, const uint32_t* b) {
    asm("mma.sync.aligned.m16n8k16.row.col.f32.f16.f16.f32 "
        "{%0,%1,%2,%3}, {%4,%5,%6,%7}, {%8,%9}, {%0,%1,%2,%3};"
        : "+f"(d[0]), "+f"(d[1]), "+f"(d[2]), "+f"(d[3])
        : "r"(a[0]), "r"(a[1]), "r"(a[2]), "r"(a[3]), "r"(b[0]), "r"(b[1]));
}
__device__ __forceinline__ void ldm4(uint32_t* r, uint32_t addr) {
    asm volatile("ldmatrix.sync.aligned.m8n8.x4.shared.b16 {%0,%1,%2,%3}, [%4];"
        : "=r"(r[0]), "=r"(r[1]), "=r"(r[2]), "=r"(r[3]) : "r"(addr));
}
__device__ __forceinline__ void ldm4t(uint32_t* r, uint32_t addr) {
    asm volatile("ldmatrix.sync.aligned.m8n8.x4.trans.shared.b16 {%0,%1,%2,%3}, [%4];"
        : "=r"(r[0]), "=r"(r[1]), "=r"(r[2]), "=r"(r[3]) : "r"(addr));
}
// pack {lo, hi} floats -> f16x2 (RN)
__device__ __forceinline__ uint32_t h2(float lo, float hi) {
    uint32_t r;
    asm("cvt.rn.f16x2.f32 %0, %1, %2;" : "=r"(r) : "f"(hi), "f"(lo));
    return r;
}
// dual-half exp2
__device__ __forceinline__ uint32_t ex2h2(uint32_t x) {
    uint32_t r;
    asm("ex2.approx.f16x2 %0, %1;" : "=r"(r) : "r"(x));
    return r;
}
__device__ __forceinline__ float ex2f(float x) {
    float r;
    asm("ex2.approx.f32 %0, %1;" : "=f"(r) : "f"(x));
    return r;
}
#define CP16(dst, src) \
    asm volatile("cp.async.cg.shared.global [%0], [%1], 16;" :: "r"(dst), "l"(src))
#define CP_COMMIT asm volatile("cp.async.commit_group;")
#define CP_WAIT(n) asm volatile("cp.async.wait_group %0;" :: "n"(n))

// ---------------------------------------------------------------------------
// x -> half
// ---------------------------------------------------------------------------
__global__ void conv_x(const float4* __restrict__ x)
{
    const int i = blockIdx.x * 256 + threadIdx.x;   // 1M float4
    float4 v = x[i];
    __half2* o = (__half2*)g_X;
    o[2*i]   = __floats2half2_rn(v.x, v.y);
    o[2*i+1] = __floats2half2_rn(v.z, v.w);
}

// ---------------------------------------------------------------------------
// Weight transpose: Wt[n][k] = half(W[k][n])
// ---------------------------------------------------------------------------
template<int N>
__global__ void transpose_k(const float* __restrict__ W)
{
    __shared__ float t[32][33];
    const int x = threadIdx.x, y = threadIdx.y;
    const int n0 = blockIdx.x * 32, k0 = blockIdx.y * 32;
    #pragma unroll
    for (int j = 0; j < 32; j += 8)
        t[y + j][x] = W[(size_t)(k0 + y + j) * N + n0 + x];
    __syncthreads();
    #pragma unroll
    for (int j = 0; j < 32; j += 8)
        g_Wt[(size_t)(n0 + y + j) * 1024 + k0 + x] = __float2half_rn(t[x][y + j]);
}

// ---------------------------------------------------------------------------
// FP16 mma GEMM: D[4096, NTOT] = A[4096,1024] x Wt^T + bias
// CTA 128x128, KC=64, 2-stage cp.async double buffer, 8 warps (2m x 4n),
// warp tile 64x32, XOR-swizzled smem (128B rows), ldmatrix fragments.
// ---------------------------------------------------------------------------
template<int NTOT, bool QKV>
__global__ __launch_bounds__(256, 2) void tgemm(const float* __restrict__ bias,
                                                float* __restrict__ out)
{
    extern __shared__ char smem[];   // 2 stages x (A 16KB + B 16KB) = 64KB
    const uint32_t sbase = smem_u32(smem);
    const int tid = threadIdx.x, lane = tid & 31, warp = tid >> 5;
    const int g = lane >> 2, t = lane & 3;
    const int q = lane >> 3, rr = lane & 7;
    const int wm = warp >> 2, wn = warp & 3;
    const int m0 = blockIdx.y * 128;
    const int n0 = blockIdx.x * 128;
    const __half* __restrict__ Ap = QKV ? (const __half*)g_X : (const __half*)g_ctx;
    const __half* __restrict__ Bp = (const __half*)g_Wt;

    auto issue = [&](int it, int st) {
        const uint32_t Ad = sbase + st * 32768;
        const uint32_t Bd = Ad + 16384;
        const int kb = it * 64;
        #pragma unroll
        for (int j = 0; j < 4; j++) {
            const int idx = tid + 256 * j;
            const int r = idx >> 3, u = idx & 7;
            const uint32_t sw = (uint32_t)r * 128 + ((u ^ (r & 7)) << 4);
            CP16(Ad + sw, Ap + (size_t)(m0 + r) * 1024 + kb + u * 8);
            CP16(Bd + sw, Bp + (size_t)(n0 + r) * 1024 + kb + u * 8);
        }
        CP_COMMIT;
    };

    float acc[4][4][4];
    #pragma unroll
    for (int mf = 0; mf < 4; mf++)
        #pragma unroll
        for (int nf = 0; nf < 4; nf++)
            #pragma unroll
            for (int c = 0; c < 4; c++) acc[mf][nf][c] = 0.0f;

    issue(0, 0);

    for (int it = 0; it < 16; ++it) {
        __syncthreads();
        if (it < 15) { issue(it + 1, (it + 1) & 1); CP_WAIT(1); }
        else         { CP_WAIT(0); }
        __syncthreads();

        const uint32_t As = sbase + (it & 1) * 32768;
        const uint32_t Bs = As + 16384;
        #pragma unroll
        for (int ks = 0; ks < 4; ks++) {
            uint32_t af[4][4], bf[2][4];
            #pragma unroll
            for (int mf = 0; mf < 4; mf++) {
                const int row = wm*64 + mf*16 + ((q & 1) << 3) + rr;
                const int u = 2*ks + (q >> 1);
                ldm4(af[mf], As + row * 128 + ((u ^ rr) << 4));
            }
            #pragma unroll
            for (int p = 0; p < 2; p++) {
                const int row = wn*32 + p*16 + ((q >> 1) << 3) + rr;
                const int u = 2*ks + (q & 1);
                ldm4(bf[p], Bs + row * 128 + ((u ^ rr) << 4));
            }
            #pragma unroll
            for (int mf = 0; mf < 4; mf++) {
                mma16(acc[mf][0], af[mf], &bf[0][0]);
                mma16(acc[mf][1], af[mf], &bf[0][2]);
                mma16(acc[mf][2], af[mf], &bf[1][0]);
                mma16(acc[mf][3], af[mf], &bf[1][2]);
            }
        }
    }

    // Epilogue
    #pragma unroll
    for (int nf = 0; nf < 4; nf++) {
        const int col = n0 + wn*32 + nf*8 + 2*t;   // even
        const float b0 = bias[col], b1 = bias[col + 1];
        if (QKV) {
            const int which = col >> 10;
            const int c = col & 1023;
            const int head = c >> 6, d0 = c & 63;
            // Q pre-scale: 1/sqrt(64) * log2(e)  (softmax runs in exp2 domain)
            const float scale = (which == 0) ? 0.125f * 1.44269504f : 1.0f;
            __half* dst = (which == 0) ? (__half*)g_Q : (which == 1) ? (__half*)g_K : (__half*)g_V;
            #pragma unroll
            for (int mf = 0; mf < 4; mf++) {
                #pragma unroll
                for (int h = 0; h < 2; h++) {
                    const int row = m0 + wm*64 + mf*16 + g + h*8;
                    const int b_ = row >> 11, s_ = row & 2047;
                    const size_t idx = ((size_t)(b_ * NHEAD + head) * SS + s_) * HD + d0;
                    *(uint32_t*)&dst[idx] = h2((acc[mf][nf][2*h]   + b0) * scale,
                                               (acc[mf][nf][2*h+1] + b1) * scale);
                }
            }
        } else {
            #pragma unroll
            for (int mf = 0; mf < 4; mf++) {
                #pragma unroll
                for (int h = 0; h < 2; h++) {
                    const int row = m0 + wm*64 + mf*16 + g + h*8;
                    float2 v;
                    v.x = acc[mf][nf][2*h]   + b0;
                    v.y = acc[mf][nf][2*h+1] + b1;
                    *(float2*)&out[(size_t)row * 1024 + col] = v;
                }
            }
        }
    }
}

// ---------------------------------------------------------------------------
// Causal flash attention v5 (fp16 mma, exp2 softmax, PAIRED q-tiles):
// CTA px handles q-tiles {px, 15-px} sequentially -> uniform 34 key-tile
// units per CTA, grid (8, 32) = 256 CTAs, one balanced wave.
// Q frags in registers; P register-resident; V ks=0 frags hoisted above
// softmax to overlap LDSM latency with the exp2 chain. 2 syncs/iter.
// ---------------------------------------------------------------------------
__global__ __launch_bounds__(256, 2) void attn_k()
{
    __shared__ char smem[32768];  // 2 stages x (K 8KB + V 8KB)
    const uint32_t sbase = smem_u32(smem);
    const int bh = blockIdx.y;
    const int px = blockIdx.x;    // 0..7
    const __half* __restrict__ Qb = (const __half*)g_Q + (size_t)bh * SS * HD;
    const __half* __restrict__ Kg = (const __half*)g_K + (size_t)bh * SS * HD;
    const __half* __restrict__ Vg = (const __half*)g_V + (size_t)bh * SS * HD;
    const int tid = threadIdx.x, lane = tid & 31, warp = tid >> 5;
    const int t = lane & 3;
    const int q = lane >> 3, rr = lane & 7;
    const int g = lane >> 2;

    auto issue = [&](int kt, int st) {
        const uint32_t Kd = sbase + st * 16384;
        const uint32_t Vd = Kd + 8192;
        const __half* Ks = Kg + (size_t)kt * 64 * HD;
        const __half* Vs = Vg + (size_t)kt * 64 * HD;
        #pragma unroll
        for (int j = 0; j < 2; j++) {
            const int idx = tid + 256 * j;
            const int r = idx >> 3, u = idx & 7;
            const uint32_t sw = (uint32_t)r * 128 + ((u ^ (r & 7)) << 4);
            CP16(Kd + sw, Ks + r * 64 + u * 8);
            CP16(Vd + sw, Vs + r * 64 + u * 8);
        }
        CP_COMMIT;
    };

    const uint32_t onesb[2] = { 0x3C003C00u, 0x3C003C00u };  // fp16 {1,1}
    const int bb = bh >> 4, hh = bh & 15;
    __half* ctx = (__half*)g_ctx;

    #pragma unroll 1
    for (int ph = 0; ph < 2; ph++) {
        const int qt = ph ? (15 - px) : px;
        const int q0 = qt * 128;
        const int ktmax = 2*qt + 1;
        const int row0g = q0 + warp*16 + g;

        // Q fragments: warp rows warp*16 + {g, g+8}, 4 k16-chunks
        uint32_t qf[4][4];
        {
            const __half* Qr = Qb + (size_t)(q0 + warp*16 + g) * 64;
            #pragma unroll
            for (int ks = 0; ks < 4; ks++) {
                qf[ks][0] = *(const uint32_t*)(Qr + ks*16 + 2*t);
                qf[ks][1] = *(const uint32_t*)(Qr + 8*64 + ks*16 + 2*t);
                qf[ks][2] = *(const uint32_t*)(Qr + ks*16 + 8 + 2*t);
                qf[ks][3] = *(const uint32_t*)(Qr + 8*64 + ks*16 + 8 + 2*t);
            }
        }

        float o[8][4];
        #pragma unroll
        for (int nf = 0; nf < 8; nf++)
            #pragma unroll
            for (int c = 0; c < 4; c++) o[nf][c] = 0.0f;
        float mr0 = -1e30f, mr1 = -1e30f, l0 = 0.0f, l1 = 0.0f;

        __syncthreads();           // phase-0 smem reads done before re-priming
        issue(0, 0);

        for (int kt = 0; kt <= ktmax; kt++) {
            __syncthreads();
            if (kt < ktmax) { issue(kt + 1, (kt + 1) & 1); CP_WAIT(1); }
            else            { CP_WAIT(0); }
            __syncthreads();

            const uint32_t Kst = sbase + (kt & 1) * 16384;
            const uint32_t Vst = Kst + 8192;
            const bool act = (kt*64 <= q0 + warp*16 + 15);
            if (!act) continue;   // no smem writes below; syncs stay aligned

            // ---- S = Q K^T (exp2 domain, scale folded into Q) ----
            float sc[8][4];
            #pragma unroll
            for (int nf = 0; nf < 8; nf++)
                #pragma unroll
                for (int c = 0; c < 4; c++) sc[nf][c] = 0.0f;
            #pragma unroll
            for (int ks = 0; ks < 4; ks++) {
                #pragma unroll
                for (int np = 0; np < 4; np++) {
                    uint32_t kb[4];
                    const int row = np*16 + ((q >> 1) << 3) + rr;
                    const int u = 2*ks + (q & 1);
                    ldm4(kb, Kst + row * 128 + ((u ^ rr) << 4));
                    mma16(sc[2*np],   qf[ks], &kb[0]);
                    mma16(sc[2*np+1], qf[ks], &kb[2]);
                }
            }
            // ---- causal mask (last two key tiles only) ----
            if (kt >= 2*qt) {
                #pragma unroll
                for (int nf = 0; nf < 8; nf++) {
                    const int key = kt*64 + nf*8 + 2*t;
                    if (key     > row0g)     sc[nf][0] = -1e30f;
                    if (key + 1 > row0g)     sc[nf][1] = -1e30f;
                    if (key     > row0g + 8) sc[nf][2] = -1e30f;
                    if (key + 1 > row0g + 8) sc[nf][3] = -1e30f;
                }
            }
            // ---- hoisted V fragments for ks=0 (overlap LDSM with softmax) ----
            uint32_t vb0[4][4];
            #pragma unroll
            for (int np = 0; np < 4; np++) {
                const int row = ((q & 1) << 3) + rr;         // ks = 0
                const int u = 2*np + (q >> 1);
                ldm4t(vb0[np], Vst + row * 128 + ((u ^ rr) << 4));
            }
            // ---- online max (rows g, g+8; quad reduce) ----
            float mx0 = -1e30f, mx1 = -1e30f;
            #pragma unroll
            for (int nf = 0; nf < 8; nf++) {
                mx0 = fmaxf(mx0, fmaxf(sc[nf][0], sc[nf][1]));
                mx1 = fmaxf(mx1, fmaxf(sc[nf][2], sc[nf][3]));
            }
            mx0 = fmaxf(mx0, __shfl_xor_sync(0xffffffffu, mx0, 1));
            mx0 = fmaxf(mx0, __shfl_xor_sync(0xffffffffu, mx0, 2));
            mx1 = fmaxf(mx1, __shfl_xor_sync(0xffffffffu, mx1, 1));
            mx1 = fmaxf(mx1, __shfl_xor_sync(0xffffffffu, mx1, 2));
            const float nm0 = fmaxf(mr0, mx0);
            const float nm1 = fmaxf(mr1, mx1);
            const float c0 = ex2f(mr0 - nm0);
            const float c1 = ex2f(mr1 - nm1);
            mr0 = nm0; mr1 = nm1;
            #pragma unroll
            for (int nf = 0; nf < 8; nf++) {
                o[nf][0] *= c0; o[nf][1] *= c0;
                o[nf][2] *= c1; o[nf][3] *= c1;
            }
            // ---- P = exp2(s - m) directly into fp16 A-fragments ----
            uint32_t pa[4][4];
            #pragma unroll
            for (int ks = 0; ks < 4; ks++) {
                pa[ks][0] = ex2h2(h2(sc[2*ks][0]   - nm0, sc[2*ks][1]   - nm0));
                pa[ks][1] = ex2h2(h2(sc[2*ks][2]   - nm1, sc[2*ks][3]   - nm1));
                pa[ks][2] = ex2h2(h2(sc[2*ks+1][0] - nm0, sc[2*ks+1][1] - nm0));
                pa[ks][3] = ex2h2(h2(sc[2*ks+1][2] - nm1, sc[2*ks+1][3] - nm1));
            }
            // ---- O += P V;  row sums via ones-column mma ----
            float ls[4] = { 0.0f, 0.0f, 0.0f, 0.0f };
            #pragma unroll
            for (int ks = 0; ks < 4; ks++) {
                mma16(ls, pa[ks], onesb);
                #pragma unroll
                for (int np = 0; np < 4; np++) {
                    uint32_t vb[4];
                    if (ks == 0) {
                        vb[0] = vb0[np][0]; vb[1] = vb0[np][1];
                        vb[2] = vb0[np][2]; vb[3] = vb0[np][3];
                    } else {
                        const int row = 16*ks + ((q & 1) << 3) + rr;
                        const int u = 2*np + (q >> 1);
                        ldm4t(vb, Vst + row * 128 + ((u ^ rr) << 4));
                    }
                    mma16(o[2*np],   pa[ks], &vb[0]);
                    mma16(o[2*np+1], pa[ks], &vb[2]);
                }
            }
            l0 = l0 * c0 + ls[0];
            l1 = l1 * c1 + ls[2];
        }

        // ---- epilogue: ctx as half ----
        const float i0 = 1.0f / l0, i1 = 1.0f / l1;
        #pragma unroll
        for (int nf = 0; nf < 8; nf++) {
            const int col = hh*64 + nf*8 + 2*t;
            const size_t b0 = (size_t)(bb * SS + row0g) * HH + col;
            const size_t b1 = (size_t)(bb * SS + row0g + 8) * HH + col;
            *(uint32_t*)&ctx[b0] = h2(o[nf][0] * i0, o[nf][1] * i0);
            *(uint32_t*)&ctx[b1] = h2(o[nf][2] * i1, o[nf][3] * i1);
        }
    }
}

// ---------------------------------------------------------------------------
extern "C" void kernel_launch(void* const* d_in, const int* in_sizes, int n_in,
                              void* d_out, int out_size)
{
    const float* x     = (const float*)d_in[0];
    // d_in[1] = mask: exactly tril(ones); causal handled analytically.
    const float* W_qkv = (const float*)d_in[2];
    const float* b_qkv = (const float*)d_in[3];
    const float* W_o   = (const float*)d_in[4];
    const float* b_o   = (const float*)d_in[5];
    float* out = (float*)d_out;

    static bool attrs_set = false;
    if (!attrs_set) {
        cudaFuncSetAttribute(tgemm<3072, true>,  cudaFuncAttributeMaxDynamicSharedMemorySize, 65536);
        cudaFuncSetAttribute(tgemm<1024, false>, cudaFuncAttributeMaxDynamicSharedMemorySize, 65536);
        attrs_set = true;
    }

    // 0) round x to fp16
    conv_x<<<4096, 256>>>((const float4*)x);

    // 1) W_qkv^T (half), then QKV projection + bias + head scatter + Q scale
    transpose_k<3072><<<dim3(96, 32), dim3(32, 8)>>>(W_qkv);
    tgemm<3072, true><<<dim3(24, 32), 256, 65536>>>(b_qkv, nullptr);

    // 2) Causal flash attention (fp16 mma, paired q-tiles, exp2 softmax)
    attn_k<<<dim3(8, 32), 256>>>();

    // 3) W_o^T (half), then output projection + bias (fp32 out)
    transpose_k<1024><<<dim3(32, 32), dim3(32, 8)>>>(W_o);
    tgemm<1024, false><<<dim3(8, 32), 256, 65536>>>(b_o, out);
}

// round 9
// speedup vs baseline: 10.1962x; 1.0002x over previous
#include <cuda_runtime.h>
#include <cuda_fp16.h>
#include <cstdint>

#define NB 2
#define SS 2048
#define HH 1024
#define NHEAD 16
#define HD 64
#define TOK (NB*SS)

// Scratch (device globals; no runtime allocation). All fp16 pre-rounded.
__device__ __half g_X[TOK*HH];            // x rounded to half
__device__ __half g_Q[NB*NHEAD*SS*HD];    // [b,h,s,d], pre-scaled by log2e/sqrt(64)
__device__ __half g_K[NB*NHEAD*SS*HD];
__device__ __half g_V[NB*NHEAD*SS*HD];
__device__ __half g_ctx[TOK*HH];          // [b*s, h]
__device__ __half g_Wt[4096*1024];        // W_qkv^T at 0, W_o^T at 3072*1024

// ---------------------------------------------------------------------------
// helpers: fp16 mma m16n8k16 (fp32 acc), ldmatrix, cp.async
// ---------------------------------------------------------------------------
__device__ __forceinline__ uint32_t smem_u32(const void* p) {
    uint32_t a;
    asm("{ .reg .u64 t; cvta.to.shared.u64 t, %1; cvt.u32.u64 %0, t; }" : "=r"(a) : "l"(p));
    return a;
}
// pure register op — non-volatile so the compiler can schedule freely
__device__ __forceinline__ void mma16(float* d, const uint32_t* a, const uint32_t* b) {
    asm("mma.sync.aligned.m16n8k16.row.col.f32.f16.f16.f32 "
        "{%0,%1,%2,%3}, {%4,%5,%6,%7}, {%8,%9}, {%0,%1,%2,%3};"
        : "+f"(d[0]), "+f"(d[1]), "+f"(d[2]), "+f"(d[3])
        : "r"(a[0]), "r"(a[1]), "r"(a[2]), "r"(a[3]), "r"(b[0]), "r"(b[1]));
}
__device__ __forceinline__ void ldm4(uint32_t* r, uint32_t addr) {
    asm volatile("ldmatrix.sync.aligned.m8n8.x4.shared.b16 {%0,%1,%2,%3}, [%4];"
        : "=r"(r[0]), "=r"(r[1]), "=r"(r[2]), "=r"(r[3]) : "r"(addr));
}
__device__ __forceinline__ void ldm4t(uint32_t* r, uint32_t addr) {
    asm volatile("ldmatrix.sync.aligned.m8n8.x4.trans.shared.b16 {%0,%1,%2,%3}, [%4];"
        : "=r"(r[0]), "=r"(r[1]), "=r"(r[2]), "=r"(r[3]) : "r"(addr));
}
// pack {lo, hi} floats -> f16x2 (RN)
__device__ __forceinline__ uint32_t h2(float lo, float hi) {
    uint32_t r;
    asm("cvt.rn.f16x2.f32 %0, %1, %2;" : "=r"(r) : "f"(hi), "f"(lo));
    return r;
}
// dual-half exp2
__device__ __forceinline__ uint32_t ex2h2(uint32_t x) {
    uint32_t r;
    asm("ex2.approx.f16x2 %0, %1;" : "=r"(r) : "r"(x));
    return r;
}
__device__ __forceinline__ float ex2f(float x) {
    float r;
    asm("ex2.approx.f32 %0, %1;" : "=f"(r) : "f"(x));
    return r;
}
#define CP16(dst, src) \
    asm volatile("cp.async.cg.shared.global [%0], [%1], 16;" :: "r"(dst), "l"(src))
#define CP_COMMIT asm volatile("cp.async.commit_group;")
#define CP_WAIT(n) asm volatile("cp.async.wait_group %0;" :: "n"(n))

// ---------------------------------------------------------------------------
// prep: x -> half (blocks 0..4095), W_qkv^T (4096..7167), W_o^T (7168..8191)
// ---------------------------------------------------------------------------
__global__ __launch_bounds__(256) void prep(const float4* __restrict__ x,
                                            const float* __restrict__ Wq,
                                            const float* __restrict__ Wo)
{
    __shared__ float t[32][33];
    const int b = blockIdx.x, tid = threadIdx.x;
    if (b < 4096) {
        const int i = b * 256 + tid;
        float4 v = x[i];
        __half2* o = (__half2*)g_X;
        o[2*i]   = __floats2half2_rn(v.x, v.y);
        o[2*i+1] = __floats2half2_rn(v.z, v.w);
        return;
    }
    const int xx = tid & 31, yy = tid >> 5;   // 32 x 8
    const float* W;
    __half* dst;
    int N, n0, k0;
    if (b < 4096 + 3072) {
        const int bb = b - 4096;
        W = Wq; dst = (__half*)g_Wt; N = 3072;
        n0 = (bb % 96) * 32; k0 = (bb / 96) * 32;
    } else {
        const int bb = b - 7168;
        W = Wo; dst = (__half*)g_Wt + 3072*1024; N = 1024;
        n0 = (bb % 32) * 32; k0 = (bb / 32) * 32;
    }
    #pragma unroll
    for (int j = 0; j < 32; j += 8)
        t[yy + j][xx] = W[(size_t)(k0 + yy + j) * N + n0 + xx];
    __syncthreads();
    #pragma unroll
    for (int j = 0; j < 32; j += 8)
        dst[(size_t)(n0 + yy + j) * 1024 + k0 + xx] = __float2half_rn(t[xx][yy + j]);
}

// ---------------------------------------------------------------------------
// FP16 mma GEMM: D[4096, NTOT] = A[4096,1024] x Wt^T + bias
// CTA 128x128, KC=64, 3-stage cp.async ring, ONE sync/iter, 8 warps (2m x 4n),
// warp tile 64x32, XOR-swizzled smem (128B rows), ldmatrix fragments.
// ---------------------------------------------------------------------------
template<int NTOT, bool QKV>
__global__ __launch_bounds__(256, 2) void tgemm(const float* __restrict__ bias,
                                                float* __restrict__ out)
{
    extern __shared__ char smem[];   // 3 stages x (A 16KB + B 16KB) = 96KB
    const uint32_t sbase = smem_u32(smem);
    const int tid = threadIdx.x, lane = tid & 31, warp = tid >> 5;
    const int g = lane >> 2, t = lane & 3;
    const int q = lane >> 3, rr = lane & 7;
    const int wm = warp >> 2, wn = warp & 3;
    const int m0 = blockIdx.y * 128;
    const int n0 = blockIdx.x * 128;
    const __half* __restrict__ Ap = QKV ? (const __half*)g_X : (const __half*)g_ctx;
    const __half* __restrict__ Bp = QKV ? (const __half*)g_Wt
                                        : (const __half*)g_Wt + 3072*1024;

    auto issue = [&](int it) {
        const uint32_t Ad = sbase + (it % 3) * 32768;
        const uint32_t Bd = Ad + 16384;
        const int kb = it * 64;
        #pragma unroll
        for (int j = 0; j < 4; j++) {
            const int idx = tid + 256 * j;
            const int r = idx >> 3, u = idx & 7;
            const uint32_t sw = (uint32_t)r * 128 + ((u ^ (r & 7)) << 4);
            CP16(Ad + sw, Ap + (size_t)(m0 + r) * 1024 + kb + u * 8);
            CP16(Bd + sw, Bp + (size_t)(n0 + r) * 1024 + kb + u * 8);
        }
        CP_COMMIT;
    };

    float acc[4][4][4];
    #pragma unroll
    for (int mf = 0; mf < 4; mf++)
        #pragma unroll
        for (int nf = 0; nf < 4; nf++)
            #pragma unroll
            for (int c = 0; c < 4; c++) acc[mf][nf][c] = 0.0f;

    issue(0);
    issue(1);

    for (int it = 0; it < 16; ++it) {
        if (it < 15) CP_WAIT(1); else CP_WAIT(0);
        __syncthreads();                 // publish stage it; protect slot (it+2)%3
        if (it + 2 < 16) issue(it + 2);

        const uint32_t As = sbase + (it % 3) * 32768;
        const uint32_t Bs = As + 16384;
        #pragma unroll
        for (int ks = 0; ks < 4; ks++) {
            uint32_t af[4][4], bf[2][4];
            #pragma unroll
            for (int mf = 0; mf < 4; mf++) {
                const int row = wm*64 + mf*16 + ((q & 1) << 3) + rr;
                const int u = 2*ks + (q >> 1);
                ldm4(af[mf], As + row * 128 + ((u ^ rr) << 4));
            }
            #pragma unroll
            for (int p = 0; p < 2; p++) {
                const int row = wn*32 + p*16 + ((q >> 1) << 3) + rr;
                const int u = 2*ks + (q & 1);
                ldm4(bf[p], Bs + row * 128 + ((u ^ rr) << 4));
            }
            #pragma unroll
            for (int mf = 0; mf < 4; mf++) {
                mma16(acc[mf][0], af[mf], &bf[0][0]);
                mma16(acc[mf][1], af[mf], &bf[0][2]);
                mma16(acc[mf][2], af[mf], &bf[1][0]);
                mma16(acc[mf][3], af[mf], &bf[1][2]);
            }
        }
    }

    // Epilogue
    #pragma unroll
    for (int nf = 0; nf < 4; nf++) {
        const int col = n0 + wn*32 + nf*8 + 2*t;   // even
        const float b0 = bias[col], b1 = bias[col + 1];
        if (QKV) {
            const int which = col >> 10;
            const int c = col & 1023;
            const int head = c >> 6, d0 = c & 63;
            // Q pre-scale: 1/sqrt(64) * log2(e)  (softmax runs in exp2 domain)
            const float scale = (which == 0) ? 0.125f * 1.44269504f : 1.0f;
            __half* dst = (which == 0) ? (__half*)g_Q : (which == 1) ? (__half*)g_K : (__half*)g_V;
            #pragma unroll
            for (int mf = 0; mf < 4; mf++) {
                #pragma unroll
                for (int h = 0; h < 2; h++) {
                    const int row = m0 + wm*64 + mf*16 + g + h*8;
                    const int b_ = row >> 11, s_ = row & 2047;
                    const size_t idx = ((size_t)(b_ * NHEAD + head) * SS + s_) * HD + d0;
                    *(uint32_t*)&dst[idx] = h2((acc[mf][nf][2*h]   + b0) * scale,
                                               (acc[mf][nf][2*h+1] + b1) * scale);
                }
            }
        } else {
            #pragma unroll
            for (int mf = 0; mf < 4; mf++) {
                #pragma unroll
                for (int h = 0; h < 2; h++) {
                    const int row = m0 + wm*64 + mf*16 + g + h*8;
                    float2 v;
                    v.x = acc[mf][nf][2*h]   + b0;
                    v.y = acc[mf][nf][2*h+1] + b1;
                    *(float2*)&out[(size_t)row * 1024 + col] = v;
                }
            }
        }
    }
}

// ---------------------------------------------------------------------------
// Causal flash attention v6 (fp16 mma, exp2 softmax, paired q-tiles,
// 3-stage cp.async ring with ONE sync/iter).
// ---------------------------------------------------------------------------
__global__ __launch_bounds__(256, 2) void attn_k()
{
    __shared__ char smem[49152];  // 3 stages x (K 8KB + V 8KB)
    const uint32_t sbase = smem_u32(smem);
    const int bh = blockIdx.y;
    const int px = blockIdx.x;    // 0..7
    const __half* __restrict__ Qb = (const __half*)g_Q + (size_t)bh * SS * HD;
    const __half* __restrict__ Kg = (const __half*)g_K + (size_t)bh * SS * HD;
    const __half* __restrict__ Vg = (const __half*)g_V + (size_t)bh * SS * HD;
    const int tid = threadIdx.x, lane = tid & 31, warp = tid >> 5;
    const int t = lane & 3;
    const int q = lane >> 3, rr = lane & 7;
    const int g = lane >> 2;

    auto issue = [&](int kt) {
        const uint32_t Kd = sbase + (kt % 3) * 16384;
        const uint32_t Vd = Kd + 8192;
        const __half* Ks = Kg + (size_t)kt * 64 * HD;
        const __half* Vs = Vg + (size_t)kt * 64 * HD;
        #pragma unroll
        for (int j = 0; j < 2; j++) {
            const int idx = tid + 256 * j;
            const int r = idx >> 3, u = idx & 7;
            const uint32_t sw = (uint32_t)r * 128 + ((u ^ (r & 7)) << 4);
            CP16(Kd + sw, Ks + r * 64 + u * 8);
            CP16(Vd + sw, Vs + r * 64 + u * 8);
        }
        CP_COMMIT;
    };

    const uint32_t onesb[2] = { 0x3C003C00u, 0x3C003C00u };  // fp16 {1,1}
    const int bb = bh >> 4, hh = bh & 15;
    __half* ctx = (__half*)g_ctx;

    #pragma unroll 1
    for (int ph = 0; ph < 2; ph++) {
        const int qt = ph ? (15 - px) : px;
        const int q0 = qt * 128;
        const int ktmax = 2*qt + 1;
        const int row0g = q0 + warp*16 + g;

        // Q fragments: warp rows warp*16 + {g, g+8}, 4 k16-chunks
        uint32_t qf[4][4];
        {
            const __half* Qr = Qb + (size_t)(q0 + warp*16 + g) * 64;
            #pragma unroll
            for (int ks = 0; ks < 4; ks++) {
                qf[ks][0] = *(const uint32_t*)(Qr + ks*16 + 2*t);
                qf[ks][1] = *(const uint32_t*)(Qr + 8*64 + ks*16 + 2*t);
                qf[ks][2] = *(const uint32_t*)(Qr + ks*16 + 8 + 2*t);
                qf[ks][3] = *(const uint32_t*)(Qr + 8*64 + ks*16 + 8 + 2*t);
            }
        }

        float o[8][4];
        #pragma unroll
        for (int nf = 0; nf < 8; nf++)
            #pragma unroll
            for (int c = 0; c < 4; c++) o[nf][c] = 0.0f;
        float mr0 = -1e30f, mr1 = -1e30f, l0 = 0.0f, l1 = 0.0f;

        __syncthreads();           // prev phase smem reads done before re-priming
        issue(0);
        issue(1);

        for (int kt = 0; kt <= ktmax; kt++) {
            if (kt < ktmax) CP_WAIT(1); else CP_WAIT(0);
            __syncthreads();       // publish stage kt; protect slot (kt+2)%3
            if (kt + 2 <= ktmax) issue(kt + 2);

            const uint32_t Kst = sbase + (kt % 3) * 16384;
            const uint32_t Vst = Kst + 8192;
            const bool act = (kt*64 <= q0 + warp*16 + 15);
            if (!act) continue;   // skip compute only; sync stays at loop top

            // ---- S = Q K^T (exp2 domain, scale folded into Q) ----
            float sc[8][4];
            #pragma unroll
            for (int nf = 0; nf < 8; nf++)
                #pragma unroll
                for (int c = 0; c < 4; c++) sc[nf][c] = 0.0f;
            #pragma unroll
            for (int ks = 0; ks < 4; ks++) {
                #pragma unroll
                for (int np = 0; np < 4; np++) {
                    uint32_t kb[4];
                    const int row = np*16 + ((q >> 1) << 3) + rr;
                    const int u = 2*ks + (q & 1);
                    ldm4(kb, Kst + row * 128 + ((u ^ rr) << 4));
                    mma16(sc[2*np],   qf[ks], &kb[0]);
                    mma16(sc[2*np+1], qf[ks], &kb[2]);
                }
            }
            // ---- causal mask (last two key tiles only) ----
            if (kt >= 2*qt) {
                #pragma unroll
                for (int nf = 0; nf < 8; nf++) {
                    const int key = kt*64 + nf*8 + 2*t;
                    if (key     > row0g)     sc[nf][0] = -1e30f;
                    if (key + 1 > row0g)     sc[nf][1] = -1e30f;
                    if (key     > row0g + 8) sc[nf][2] = -1e30f;
                    if (key + 1 > row0g + 8) sc[nf][3] = -1e30f;
                }
            }
            // ---- hoisted V fragments for ks=0 (overlap LDSM with softmax) ----
            uint32_t vb0[4][4];
            #pragma unroll
            for (int np = 0; np < 4; np++) {
                const int row = ((q & 1) << 3) + rr;         // ks = 0
                const int u = 2*np + (q >> 1);
                ldm4t(vb0[np], Vst + row * 128 + ((u ^ rr) << 4));
            }
            // ---- online max (rows g, g+8; quad reduce) ----
            float mx0 = -1e30f, mx1 = -1e30f;
            #pragma unroll
            for (int nf = 0; nf < 8; nf++) {
                mx0 = fmaxf(mx0, fmaxf(sc[nf][0], sc[nf][1]));
                mx1 = fmaxf(mx1, fmaxf(sc[nf][2], sc[nf][3]));
            }
            mx0 = fmaxf(mx0, __shfl_xor_sync(0xffffffffu, mx0, 1));
            mx0 = fmaxf(mx0, __shfl_xor_sync(0xffffffffu, mx0, 2));
            mx1 = fmaxf(mx1, __shfl_xor_sync(0xffffffffu, mx1, 1));
            mx1 = fmaxf(mx1, __shfl_xor_sync(0xffffffffu, mx1, 2));
            const float nm0 = fmaxf(mr0, mx0);
            const float nm1 = fmaxf(mr1, mx1);
            const float c0 = ex2f(mr0 - nm0);
            const float c1 = ex2f(mr1 - nm1);
            mr0 = nm0; mr1 = nm1;
            #pragma unroll
            for (int nf = 0; nf < 8; nf++) {
                o[nf][0] *= c0; o[nf][1] *= c0;
                o[nf][2] *= c1; o[nf][3] *= c1;
            }
            // ---- P = exp2(s - m) directly into fp16 A-fragments ----
            uint32_t pa[4][4];
            #pragma unroll
            for (int ks = 0; ks < 4; ks++) {
                pa[ks][0] = ex2h2(h2(sc[2*ks][0]   - nm0, sc[2*ks][1]   - nm0));
                pa[ks][1] = ex2h2(h2(sc[2*ks][2]   - nm1, sc[2*ks][3]   - nm1));
                pa[ks][2] = ex2h2(h2(sc[2*ks+1][0] - nm0, sc[2*ks+1][1] - nm0));
                pa[ks][3] = ex2h2(h2(sc[2*ks+1][2] - nm1, sc[2*ks+1][3] - nm1));
            }
            // ---- O += P V;  row sums via ones-column mma ----
            float ls[4] = { 0.0f, 0.0f, 0.0f, 0.0f };
            #pragma unroll
            for (int ks = 0; ks < 4; ks++) {
                mma16(ls, pa[ks], onesb);
                #pragma unroll
                for (int np = 0; np < 4; np++) {
                    uint32_t vb[4];
                    if (ks == 0) {
                        vb[0] = vb0[np][0]; vb[1] = vb0[np][1];
                        vb[2] = vb0[np][2]; vb[3] = vb0[np][3];
                    } else {
                        const int row = 16*ks + ((q & 1) << 3) + rr;
                        const int u = 2*np + (q >> 1);
                        ldm4t(vb, Vst + row * 128 + ((u ^ rr) << 4));
                    }
                    mma16(o[2*np],   pa[ks], &vb[0]);
                    mma16(o[2*np+1], pa[ks], &vb[2]);
                }
            }
            l0 = l0 * c0 + ls[0];
            l1 = l1 * c1 + ls[2];
        }

        // ---- epilogue: ctx as half ----
        const float i0 = 1.0f / l0, i1 = 1.0f / l1;
        #pragma unroll
        for (int nf = 0; nf < 8; nf++) {
            const int col = hh*64 + nf*8 + 2*t;
            const size_t b0 = (size_t)(bb * SS + row0g) * HH + col;
            const size_t b1 = (size_t)(bb * SS + row0g + 8) * HH + col;
            *(uint32_t*)&ctx[b0] = h2(o[nf][0] * i0, o[nf][1] * i0);
            *(uint32_t*)&ctx[b1] = h2(o[nf][2] * i1, o[nf][3] * i1);
        }
    }
}

// ---------------------------------------------------------------------------
extern "C" void kernel_launch(void* const* d_in, const int* in_sizes, int n_in,
                              void* d_out, int out_size)
{
    const float* x     = (const float*)d_in[0];
    // d_in[1] = mask: exactly tril(ones); causal handled analytically.
    const float* W_qkv = (const float*)d_in[2];
    const float* b_qkv = (const float*)d_in[3];
    const float* W_o   = (const float*)d_in[4];
    const float* b_o   = (const float*)d_in[5];
    float* out = (float*)d_out;

    static bool attrs_set = false;
    if (!attrs_set) {
        cudaFuncSetAttribute(tgemm<3072, true>,  cudaFuncAttributeMaxDynamicSharedMemorySize, 98304);
        cudaFuncSetAttribute(tgemm<1024, false>, cudaFuncAttributeMaxDynamicSharedMemorySize, 98304);
        attrs_set = true;
    }

    // 0) x -> fp16, W_qkv^T, W_o^T (one merged kernel)
    prep<<<8192, 256>>>((const float4*)x, W_qkv, W_o);

    // 1) QKV projection + bias + head scatter + Q scale (fp16 mma, 3-stage)
    tgemm<3072, true><<<dim3(24, 32), 256, 98304>>>(b_qkv, nullptr);

    // 2) Causal flash attention (fp16 mma, paired q-tiles, exp2 softmax, 3-stage)
    attn_k<<<dim3(8, 32), 256>>>();

    // 3) Output projection + bias (fp32 out, 3-stage)
    tgemm<1024, false><<<dim3(8, 32), 256, 98304>>>(b_o, out);
}